// round 8
// baseline (speedup 1.0000x reference)
#include <cuda_runtime.h>
#include <cuda_bf16.h>
#include <cstdint>
#include <math.h>

// ---------------------------------------------------------------------------
// Problem constants
// ---------------------------------------------------------------------------
#define HDIM   1024
#define NAVAIL 32768
#define KFULL  2048      // GEMM0 K (the +2 scalar features handled in epilogue)
#define NOP    40000     // x_op rows
#define NM     64        // x_m rows

// GEMM tiling (mma.sync m16n8k16 bf16)
#define BM 128
#define BN 128
#define BK 16
#define NTHREADS 256     // 8 warps: 4 (M) x 2 (N)

// Packed tile format: 128 rows x 16 bf16 = 4096 B. Row stride 32 B, XOR swizzle:
//   byte(r, ch, c) = r*32 + ((ch ^ ((r>>2)&1))<<4) + c*2   (ch = 8-col chunk)
// ldmatrix bank walk over 8 rows: 0,8,16,24,4,12,20,28 -> conflict-free.
#define ST_AH 0
#define ST_AL 4096
#define ST_BH 8192
#define ST_BL 12288
#define ST_STRIDE 16384
#define SMEM_BYTES (3 * ST_STRIDE)        // 49152 = default cap, no opt-in

// ---------------------------------------------------------------------------
// Device scratch (no runtime allocation allowed)
// ---------------------------------------------------------------------------
__device__ float g_h2[(size_t)NAVAIL * HDIM];                 // layer2 out (fp32)
__device__ float g_scores[NAVAIL];
__device__ __nv_bfloat16 g_xmh[(size_t)NM * HDIM];            // x_m split
__device__ __nv_bfloat16 g_xml[(size_t)NM * HDIM];
__device__ __nv_bfloat16 g_xoh[(size_t)NOP * HDIM];           // x_op split
__device__ __nv_bfloat16 g_xol[(size_t)NOP * HDIM];
__device__ __nv_bfloat16 g_a0h[(size_t)NAVAIL * HDIM];        // layer outs (row-major)
__device__ __nv_bfloat16 g_a0l[(size_t)NAVAIL * HDIM];
__device__ __nv_bfloat16 g_a1h[(size_t)NAVAIL * HDIM];
__device__ __nv_bfloat16 g_a1l[(size_t)NAVAIL * HDIM];
__device__ __nv_bfloat16 g_wt0h[(size_t)HDIM * KFULL];        // W^T packed tiles
__device__ __nv_bfloat16 g_wt0l[(size_t)HDIM * KFULL];
__device__ __nv_bfloat16 g_wt1h[(size_t)HDIM * HDIM];
__device__ __nv_bfloat16 g_wt1l[(size_t)HDIM * HDIM];
__device__ __nv_bfloat16 g_wt2h[(size_t)HDIM * HDIM];
__device__ __nv_bfloat16 g_wt2l[(size_t)HDIM * HDIM];

// ---------------------------------------------------------------------------
// Helpers (all sm_80-era PTX; nothing arch-accelerated)
// ---------------------------------------------------------------------------
__device__ __forceinline__ uint32_t smem_u32(const void* p) {
    uint32_t a;
    asm("{ .reg .u64 t; cvta.to.shared.u64 t, %1; cvt.u32.u64 %0, t; }"
        : "=r"(a) : "l"(p));
    return a;
}
__device__ __forceinline__ void ldmx4(uint32_t* r, uint32_t addr) {
    asm volatile("ldmatrix.sync.aligned.m8n8.x4.shared.b16 {%0,%1,%2,%3}, [%4];"
                 : "=r"(r[0]), "=r"(r[1]), "=r"(r[2]), "=r"(r[3]) : "r"(addr));
}
__device__ __forceinline__ void mma_bf16(float* d, const uint32_t* a,
                                         uint32_t b0, uint32_t b1) {
    asm volatile("mma.sync.aligned.m16n8k16.row.col.f32.bf16.bf16.f32 "
                 "{%0,%1,%2,%3}, {%4,%5,%6,%7}, {%8,%9}, {%0,%1,%2,%3};"
                 : "+f"(d[0]), "+f"(d[1]), "+f"(d[2]), "+f"(d[3])
                 : "r"(a[0]), "r"(a[1]), "r"(a[2]), "r"(a[3]), "r"(b0), "r"(b1));
}
__device__ __forceinline__ void cp16(uint32_t dst, const void* src) {
    asm volatile("cp.async.cg.shared.global [%0], [%1], 16;"
                 :: "r"(dst), "l"(src) : "memory");
}
#define CP_COMMIT() asm volatile("cp.async.commit_group;" ::: "memory")
#define CP_WAIT1()  asm volatile("cp.async.wait_group 1;" ::: "memory")

__device__ __forceinline__ void split2(float a, float b, uint32_t& hi, uint32_t& lo) {
    __nv_bfloat16 ha = __float2bfloat16_rn(a);
    __nv_bfloat16 hb = __float2bfloat16_rn(b);
    __nv_bfloat16 la = __float2bfloat16_rn(a - __bfloat162float(ha));
    __nv_bfloat16 lb = __float2bfloat16_rn(b - __bfloat162float(hb));
    __nv_bfloat162 H; H.x = ha; H.y = hb;
    __nv_bfloat162 L; L.x = la; L.y = lb;
    hi = *reinterpret_cast<uint32_t*>(&H);
    lo = *reinterpret_cast<uint32_t*>(&L);
}

// ---------------------------------------------------------------------------
// Prep A: elementwise fp32 -> bf16 hi/lo (row-major), float4 per thread
// ---------------------------------------------------------------------------
__global__ void split_rows(const float* __restrict__ X, size_t n4,
                           __nv_bfloat16* __restrict__ H,
                           __nv_bfloat16* __restrict__ L) {
    const size_t i = (size_t)blockIdx.x * blockDim.x + threadIdx.x;
    if (i >= n4) return;
    const float4 v = ((const float4*)X)[i];
    uint32_t h01, l01, h23, l23;
    split2(v.x, v.y, h01, l01);
    split2(v.z, v.w, h23, l23);
    ((uint2*)H)[i] = make_uint2(h01, h23);
    ((uint2*)L)[i] = make_uint2(l01, l23);
}

// ---------------------------------------------------------------------------
// Prep W: transpose + split [K x N] fp32 into PACKED swizzled tiles:
// block (ntile, ktile) of 4096 B at ((n>>7)*(K/16) + (k>>4))*4096.
// ---------------------------------------------------------------------------
__global__ void transpose_split_pack(const float* __restrict__ W, int K, int N,
                                     __nv_bfloat16* __restrict__ Th,
                                     __nv_bfloat16* __restrict__ Tl) {
    __shared__ float tbuf[32][33];
    const int nb = blockIdx.x * 32, kb = blockIdx.y * 32;
    const int tx = threadIdx.x, ty = threadIdx.y;   // (32, 8)
    #pragma unroll
    for (int j = 0; j < 32; j += 8)
        tbuf[ty + j][tx] = W[(size_t)(kb + ty + j) * N + nb + tx];
    __syncthreads();
    #pragma unroll
    for (int j = 0; j < 32; j += 8) {
        const float x = tbuf[tx][ty + j];            // = W[kb+tx][nb+ty+j]
        const int k = kb + tx;
        const int n = nb + ty + j;
        const __nv_bfloat16 h = __float2bfloat16_rn(x);
        const __nv_bfloat16 l = __float2bfloat16_rn(x - __bfloat162float(h));
        const int lr = n & 127, kc = k & 15, ch = kc >> 3;
        const size_t off = ((size_t)(n >> 7) * (K / 16) + (k >> 4)) * 4096
                         + lr * 32 + ((ch ^ ((lr >> 2) & 1)) << 4) + (kc & 7) * 2;
        *(__nv_bfloat16*)((char*)Th + off) = h;
        *(__nv_bfloat16*)((char*)Tl + off) = l;
    }
}

// ---------------------------------------------------------------------------
// Split-bf16 GEMM layer, 3-stage cp.async pipeline. All operands bf16 hi/lo.
//   A via per-row cp.async gather (GATHER: m_ids/op_idx indirection + k-switch
//   at 1024; else identity rows). B via packed weight tiles.
//   OUTPK: write row-major bf16 hi/lo for the next layer; else fp32 rows.
// ---------------------------------------------------------------------------
template <int KTOT, bool GATHER, bool OUTPK>
__global__ __launch_bounds__(NTHREADS)
void gemm_mma_kernel(const __nv_bfloat16* __restrict__ Ah,   // GATHER: x_m hi
                     const __nv_bfloat16* __restrict__ Al,
                     const __nv_bfloat16* __restrict__ Oh,   // GATHER: x_op hi
                     const __nv_bfloat16* __restrict__ Ol,
                     const __nv_bfloat16* __restrict__ WTh,
                     const __nv_bfloat16* __restrict__ WTl,
                     const float* __restrict__ bias,
                     const float* __restrict__ W0tail,
                     const float* __restrict__ job_srpt,
                     const float* __restrict__ pt,
                     const int* __restrict__ m_ids,
                     const int* __restrict__ op_idx,
                     const int* __restrict__ job_ids,
                     void* __restrict__ outH, void* __restrict__ outL) {
    extern __shared__ char sm[];
    const uint32_t sbase = smem_u32(sm);
    const int tid = threadIdx.x, wid = tid >> 5, lane = tid & 31;
    const int wm = wid >> 1, wn = wid & 1;
    const int n0 = blockIdx.x * BN, m0 = blockIdx.y * BM;
    constexpr int T = KTOT / BK;
    constexpr int TSW = HDIM / BK;            // k-tile where L0 switches to x_op

    // B sources: packed blocks, +4096 B per k-tile
    const char* srcBh = (const char*)WTh + (size_t)(n0 >> 7) * T * 4096 + tid * 16;
    const char* srcBl = (const char*)WTl + (size_t)(n0 >> 7) * T * 4096 + tid * 16;

    // A row-gather mapping: thread -> (row, 16B chunk); 2 cp16 (hi,lo) per stage
    const int arow = tid >> 1, ach = tid & 1;
    const uint32_t ofsA = arow * 32 + ((ach ^ ((arow >> 2) & 1)) << 4);
    const char *amH, *amL, *aoH = nullptr, *aoL = nullptr;
    if constexpr (GATHER) {
        const int m = m0 + arow;
        amH = (const char*)(Ah + (size_t)m_ids[m] * HDIM) + ach * 16;
        amL = (const char*)(Al + (size_t)m_ids[m] * HDIM) + ach * 16;
        aoH = (const char*)(Oh + (size_t)op_idx[m] * HDIM) + ach * 16;
        aoL = (const char*)(Ol + (size_t)op_idx[m] * HDIM) + ach * 16;
    } else {
        amH = (const char*)(Ah + (size_t)(m0 + arow) * HDIM) + ach * 16;
        amL = (const char*)(Al + (size_t)(m0 + arow) * HDIM) + ach * 16;
    }

    float acc[2][8][4];
    #pragma unroll
    for (int i = 0; i < 2; ++i)
        #pragma unroll
        for (int j = 0; j < 8; ++j)
            #pragma unroll
            for (int r = 0; r < 4; ++r) acc[i][j][r] = 0.f;

    auto cpStage = [&](int kt, int slot) {
        const uint32_t d = sbase + slot * ST_STRIDE;
        const size_t o = (size_t)kt * 4096;
        cp16(d + ST_BH + tid * 16, srcBh + o);
        cp16(d + ST_BL + tid * 16, srcBl + o);
        const char* sh = amH;
        const char* sl = amL;
        int kk = kt;
        if constexpr (GATHER) {
            if (kt >= TSW) { sh = aoH; sl = aoL; kk = kt - TSW; }
        }
        cp16(d + ST_AH + ofsA, sh + kk * 32);
        cp16(d + ST_AL + ofsA, sl + kk * 32);
    };

    // ---- prologue ----
    cpStage(0, 0); CP_COMMIT();
    cpStage(1, 1); CP_COMMIT();

    // per-lane ldmatrix offset (row + swizzled k-chunk)
    const uint32_t lofs = (lane & 15) * 32 + (((lane >> 4) ^ ((lane >> 2) & 1)) << 4);

    for (int t = 0; t < T; ++t) {
        CP_WAIT1();                 // stage t complete (newest group may pend)
        __syncthreads();            // all warps done computing stage t-1
        if (t + 2 < T) cpStage(t + 2, (t + 2) % 3);   // refills slot (t-1)%3
        CP_COMMIT();                // unconditional: keeps wait_group(1) semantics

        const uint32_t st = sbase + (t % 3) * ST_STRIDE;
        uint32_t ah[2][4], al[2][4], bh[4][4], bl[4][4];
        #pragma unroll
        for (int mt = 0; mt < 2; ++mt) {
            const uint32_t ra = st + ST_AH + wm * 1024 + mt * 512 + lofs;
            ldmx4(ah[mt], ra);
            ldmx4(al[mt], ra + (ST_AL - ST_AH));
        }
        #pragma unroll
        for (int p = 0; p < 4; ++p) {
            const uint32_t rb = st + ST_BH + wn * 2048 + p * 512 + lofs;
            ldmx4(bh[p], rb);
            ldmx4(bl[p], rb + (ST_BL - ST_BH));
        }
        #pragma unroll
        for (int mt = 0; mt < 2; ++mt)
            #pragma unroll
            for (int nt = 0; nt < 8; ++nt) {
                const int p = nt >> 1, o = nt & 1;
                mma_bf16(acc[mt][nt], ah[mt], bh[p][o], bh[p][2 + o]);
                mma_bf16(acc[mt][nt], ah[mt], bl[p][o], bl[p][2 + o]);
                mma_bf16(acc[mt][nt], al[mt], bh[p][o], bh[p][2 + o]);
            }
    }

    // ---- epilogue ----
    const int gq = lane >> 2, tg = lane & 3;
    #pragma unroll
    for (int mt = 0; mt < 2; ++mt) {
        const int er0 = m0 + wm * 32 + mt * 16 + gq;
        const int er1 = er0 + 8;
        float js0 = 0.f, pv0 = 0.f, js1 = 0.f, pv1 = 0.f;
        if constexpr (GATHER) {
            js0 = job_srpt[job_ids[er0]]; pv0 = pt[er0];
            js1 = job_srpt[job_ids[er1]]; pv1 = pt[er1];
        }
        #pragma unroll
        for (int nt = 0; nt < 8; ++nt) {
            const int nc = n0 + wn * 64 + nt * 8 + tg * 2;
            const float bz0 = bias[nc], bz1 = bias[nc + 1];
            float e00 = 0.f, e01 = 0.f, e10 = 0.f, e11 = 0.f;
            if constexpr (GATHER) {
                const float wa0 = W0tail[nc], wa1 = W0tail[nc + 1];
                const float wb0 = W0tail[HDIM + nc], wb1 = W0tail[HDIM + nc + 1];
                e00 = js0 * wa0 + pv0 * wb0; e01 = js0 * wa1 + pv0 * wb1;
                e10 = js1 * wa0 + pv1 * wb0; e11 = js1 * wa1 + pv1 * wb1;
            }
            float v00 = acc[mt][nt][0] + bz0 + e00;
            float v01 = acc[mt][nt][1] + bz1 + e01;
            float v10 = acc[mt][nt][2] + bz0 + e10;
            float v11 = acc[mt][nt][3] + bz1 + e11;
            v00 = v00 > 0.f ? v00 : 0.01f * v00;
            v01 = v01 > 0.f ? v01 : 0.01f * v01;
            v10 = v10 > 0.f ? v10 : 0.01f * v10;
            v11 = v11 > 0.f ? v11 : 0.01f * v11;
            if constexpr (OUTPK) {
                // row-major bf16 hi/lo for the next layer's A gather
                uint32_t h0, l0, h1, l1;
                split2(v00, v01, h0, l0);
                split2(v10, v11, h1, l1);
                __nv_bfloat16* oh = (__nv_bfloat16*)outH;
                __nv_bfloat16* ol = (__nv_bfloat16*)outL;
                *(uint32_t*)(oh + (size_t)er0 * HDIM + nc) = h0;
                *(uint32_t*)(ol + (size_t)er0 * HDIM + nc) = l0;
                *(uint32_t*)(oh + (size_t)er1 * HDIM + nc) = h1;
                *(uint32_t*)(ol + (size_t)er1 * HDIM + nc) = l1;
            } else {
                float* out = (float*)outH;
                *(float2*)(out + (size_t)er0 * HDIM + nc) = make_float2(v00, v01);
                *(float2*)(out + (size_t)er1 * HDIM + nc) = make_float2(v10, v11);
            }
        }
    }
}

// ---------------------------------------------------------------------------
// Final layer GEMV: scores[m] = h[m,:] . W3 + b3
// ---------------------------------------------------------------------------
__global__ void gemv_kernel(const float* __restrict__ hbuf,
                            const float* __restrict__ W3,
                            const float* __restrict__ b3,
                            float* __restrict__ scores) {
    const int gw = (int)((blockIdx.x * blockDim.x + threadIdx.x) >> 5);
    const int lane = threadIdx.x & 31;
    if (gw >= NAVAIL) return;
    const float4* hr = (const float4*)(hbuf + (size_t)gw * HDIM);
    const float4* wr = (const float4*)W3;
    float s = 0.f;
    #pragma unroll 4
    for (int i = lane; i < HDIM / 4; i += 32) {
        const float4 a = hr[i];
        const float4 w = wr[i];
        s += a.x * w.x + a.y * w.y + a.z * w.z + a.w * w.w;
    }
    #pragma unroll
    for (int off = 16; off > 0; off >>= 1)
        s += __shfl_down_sync(0xffffffffu, s, off);
    if (lane == 0) scores[gw] = s + b3[0];
}

// ---------------------------------------------------------------------------
// Softmax + argmax (first-max semantics), single block.
// ---------------------------------------------------------------------------
__global__ void softmax_kernel(const float* __restrict__ scores,
                               float* __restrict__ out, int out_size) {
    const int tid = threadIdx.x;
    const int lane = tid & 31;
    const int wid = tid >> 5;
    __shared__ float red_f[32];
    __shared__ int   red_i[32];
    __shared__ float red_s[32];

    float bmax = -INFINITY;
    int bidx = 0x7fffffff;
    for (int i = tid; i < NAVAIL; i += 1024) {
        const float v = scores[i];
        if (v > bmax) { bmax = v; bidx = i; }
    }
    #pragma unroll
    for (int off = 16; off > 0; off >>= 1) {
        const float om = __shfl_down_sync(0xffffffffu, bmax, off);
        const int oi = __shfl_down_sync(0xffffffffu, bidx, off);
        if (om > bmax || (om == bmax && oi < bidx)) { bmax = om; bidx = oi; }
    }
    if (lane == 0) { red_f[wid] = bmax; red_i[wid] = bidx; }
    __syncthreads();
    if (tid < 32) {
        bmax = red_f[tid];
        bidx = red_i[tid];
        #pragma unroll
        for (int off = 16; off > 0; off >>= 1) {
            const float om = __shfl_down_sync(0xffffffffu, bmax, off);
            const int oi = __shfl_down_sync(0xffffffffu, bidx, off);
            if (om > bmax || (om == bmax && oi < bidx)) { bmax = om; bidx = oi; }
        }
        if (tid == 0) { red_f[0] = bmax; red_i[0] = bidx; }
    }
    __syncthreads();
    const float gmax = red_f[0];
    const int gidx = red_i[0];

    float s = 0.f;
    for (int i = tid; i < NAVAIL; i += 1024) {
        const float e = expf(scores[i] - gmax);
        out[i] = e;
        s += e;
    }
    #pragma unroll
    for (int off = 16; off > 0; off >>= 1)
        s += __shfl_down_sync(0xffffffffu, s, off);
    if (lane == 0) red_s[wid] = s;
    __syncthreads();
    if (tid < 32) {
        s = red_s[tid];
        #pragma unroll
        for (int off = 16; off > 0; off >>= 1)
            s += __shfl_down_sync(0xffffffffu, s, off);
        if (tid == 0) red_s[0] = s;
    }
    __syncthreads();
    const float inv = 1.0f / red_s[0];
    for (int i = tid; i < NAVAIL; i += 1024)
        out[i] *= inv;
    for (int i = NAVAIL + tid; i < out_size; i += 1024)
        out[i] = (float)gidx;
}

// ---------------------------------------------------------------------------
// Launch. inputs: x_m, x_op, job_srpt, pt, W0, b0, W1, b1, W2, b2, W3, b3,
//                 m_ids, op_idx, job_ids
// Host API surface: cudaGetSymbolAddress + launches only (R5/R6-proven).
// ---------------------------------------------------------------------------
extern "C" void kernel_launch(void* const* d_in, const int* in_sizes, int n_in,
                              void* d_out, int out_size) {
    const float* x_m      = (const float*)d_in[0];
    const float* x_op     = (const float*)d_in[1];
    const float* job_srpt = (const float*)d_in[2];
    const float* pt       = (const float*)d_in[3];
    const float* W0       = (const float*)d_in[4];
    const float* b0       = (const float*)d_in[5];
    const float* W1       = (const float*)d_in[6];
    const float* b1       = (const float*)d_in[7];
    const float* W2       = (const float*)d_in[8];
    const float* b2       = (const float*)d_in[9];
    const float* W3       = (const float*)d_in[10];
    const float* b3       = (const float*)d_in[11];
    const int*   m_ids    = (const int*)d_in[12];
    const int*   op_idx   = (const int*)d_in[13];
    const int*   job_ids  = (const int*)d_in[14];
    float* out = (float*)d_out;

    float *h2, *sc;
    __nv_bfloat16 *xmh, *xml, *xoh, *xol, *a0h, *a0l, *a1h, *a1l;
    __nv_bfloat16 *w0h, *w0l, *w1h, *w1l, *w2h, *w2l;
    cudaGetSymbolAddress((void**)&h2, g_h2);
    cudaGetSymbolAddress((void**)&sc, g_scores);
    cudaGetSymbolAddress((void**)&xmh, g_xmh);
    cudaGetSymbolAddress((void**)&xml, g_xml);
    cudaGetSymbolAddress((void**)&xoh, g_xoh);
    cudaGetSymbolAddress((void**)&xol, g_xol);
    cudaGetSymbolAddress((void**)&a0h, g_a0h);
    cudaGetSymbolAddress((void**)&a0l, g_a0l);
    cudaGetSymbolAddress((void**)&a1h, g_a1h);
    cudaGetSymbolAddress((void**)&a1l, g_a1l);
    cudaGetSymbolAddress((void**)&w0h, g_wt0h);
    cudaGetSymbolAddress((void**)&w0l, g_wt0l);
    cudaGetSymbolAddress((void**)&w1h, g_wt1h);
    cudaGetSymbolAddress((void**)&w1l, g_wt1l);
    cudaGetSymbolAddress((void**)&w2h, g_wt2h);
    cudaGetSymbolAddress((void**)&w2l, g_wt2l);

    // prep: split activations + pack weights (off critical path, ~70us)
    {
        const size_t nm4 = (size_t)NM * HDIM / 4;
        const size_t no4 = (size_t)NOP * HDIM / 4;
        split_rows<<<(int)((nm4 + 255) / 256), 256>>>(x_m, nm4, xmh, xml);
        split_rows<<<(int)((no4 + 255) / 256), 256>>>(x_op, no4, xoh, xol);
        dim3 thr(32, 8);
        transpose_split_pack<<<dim3(HDIM / 32, KFULL / 32), thr>>>(W0, KFULL, HDIM, w0h, w0l);
        transpose_split_pack<<<dim3(HDIM / 32, HDIM / 32), thr>>>(W1, HDIM, HDIM, w1h, w1l);
        transpose_split_pack<<<dim3(HDIM / 32, HDIM / 32), thr>>>(W2, HDIM, HDIM, w2h, w2l);
    }

    const dim3 grid(HDIM / BN, NAVAIL / BM);   // (8, 256)
    const float* W0tail = W0 + (size_t)KFULL * HDIM;   // rows 2048, 2049

    gemm_mma_kernel<KFULL, true, true><<<grid, NTHREADS, SMEM_BYTES>>>(
        xmh, xml, xoh, xol, w0h, w0l, b0, W0tail, job_srpt, pt,
        m_ids, op_idx, job_ids, a0h, a0l);
    gemm_mma_kernel<HDIM, false, true><<<grid, NTHREADS, SMEM_BYTES>>>(
        a0h, a0l, nullptr, nullptr, w1h, w1l, b1, nullptr, nullptr, nullptr,
        nullptr, nullptr, nullptr, a1h, a1l);
    gemm_mma_kernel<HDIM, false, false><<<grid, NTHREADS, SMEM_BYTES>>>(
        a1h, a1l, nullptr, nullptr, w2h, w2l, b2, nullptr, nullptr, nullptr,
        nullptr, nullptr, nullptr, h2, nullptr);

    gemv_kernel<<<NAVAIL / 8, 256>>>(h2, W3, b3, sc);
    softmax_kernel<<<1, 1024>>>(sc, out, out_size);
}

// round 11
// speedup vs baseline: 1.1489x; 1.1489x over previous
#include <cuda_runtime.h>
#include <cuda_bf16.h>
#include <cstdint>
#include <math.h>

// ---------------------------------------------------------------------------
// Problem constants
// ---------------------------------------------------------------------------
#define HDIM   1024
#define NAVAIL 32768
#define KFULL  2048      // GEMM0 K (the +2 scalar features handled in epilogue)
#define NOP    40000     // x_op rows
#define NM     64        // x_m rows

// GEMM tiling (mma.sync m16n8k16 bf16)
#define BM 128
#define BN 128
#define BK 16
#define NTHREADS 256     // 8 warps: 4 (M) x 2 (N)

// Packed tile format (R6-proven): per k-16 block of 4096 B, row stride 32 B:
//   byte(r, ch, c) = r*32 + ((ch ^ ((r>>2)&1))<<4) + c*2   (ch = 8-col chunk)
// ldmatrix bank walk over 8 rows: 0,8,16,24,4,12,20,28 -> conflict-free.
#define ST_AH 0
#define ST_AL 4096
#define ST_BH 8192
#define ST_BL 12288
#define ST_STRIDE 16384
#define SMEM_BYTES (3 * ST_STRIDE)   // 49152 = default cap: NO attr call (hard rule)

// ---------------------------------------------------------------------------
// Device scratch (no runtime allocation allowed)
// ---------------------------------------------------------------------------
__device__ float g_h2[(size_t)NAVAIL * HDIM];                 // layer2 out (fp32)
__device__ float g_scores[NAVAIL];
__device__ __nv_bfloat16 g_xmh[(size_t)NM * HDIM];            // x_m split (row-major)
__device__ __nv_bfloat16 g_xml[(size_t)NM * HDIM];
__device__ __nv_bfloat16 g_xoh[(size_t)NOP * HDIM];           // x_op split (row-major)
__device__ __nv_bfloat16 g_xol[(size_t)NOP * HDIM];
__device__ __nv_bfloat16 g_a0h[(size_t)NAVAIL * HDIM];        // layer outs (PACKED tiles)
__device__ __nv_bfloat16 g_a0l[(size_t)NAVAIL * HDIM];
__device__ __nv_bfloat16 g_a1h[(size_t)NAVAIL * HDIM];
__device__ __nv_bfloat16 g_a1l[(size_t)NAVAIL * HDIM];
__device__ __nv_bfloat16 g_wt0h[(size_t)HDIM * KFULL];        // W^T packed tiles
__device__ __nv_bfloat16 g_wt0l[(size_t)HDIM * KFULL];
__device__ __nv_bfloat16 g_wt1h[(size_t)HDIM * HDIM];
__device__ __nv_bfloat16 g_wt1l[(size_t)HDIM * HDIM];
__device__ __nv_bfloat16 g_wt2h[(size_t)HDIM * HDIM];
__device__ __nv_bfloat16 g_wt2l[(size_t)HDIM * HDIM];

// ---------------------------------------------------------------------------
// Helpers (all sm_80-era PTX; nothing arch-accelerated)
// ---------------------------------------------------------------------------
__device__ __forceinline__ uint32_t smem_u32(const void* p) {
    uint32_t a;
    asm("{ .reg .u64 t; cvta.to.shared.u64 t, %1; cvt.u32.u64 %0, t; }"
        : "=r"(a) : "l"(p));
    return a;
}
__device__ __forceinline__ void ldmx4(uint32_t* r, uint32_t addr) {
    asm volatile("ldmatrix.sync.aligned.m8n8.x4.shared.b16 {%0,%1,%2,%3}, [%4];"
                 : "=r"(r[0]), "=r"(r[1]), "=r"(r[2]), "=r"(r[3]) : "r"(addr));
}
__device__ __forceinline__ void mma_bf16(float* d, const uint32_t* a,
                                         uint32_t b0, uint32_t b1) {
    asm volatile("mma.sync.aligned.m16n8k16.row.col.f32.bf16.bf16.f32 "
                 "{%0,%1,%2,%3}, {%4,%5,%6,%7}, {%8,%9}, {%0,%1,%2,%3};"
                 : "+f"(d[0]), "+f"(d[1]), "+f"(d[2]), "+f"(d[3])
                 : "r"(a[0]), "r"(a[1]), "r"(a[2]), "r"(a[3]), "r"(b0), "r"(b1));
}
__device__ __forceinline__ void cp16(uint32_t dst, const void* src) {
    asm volatile("cp.async.cg.shared.global [%0], [%1], 16;"
                 :: "r"(dst), "l"(src) : "memory");
}
#define CP_COMMIT() asm volatile("cp.async.commit_group;" ::: "memory")
#define CP_WAIT1()  asm volatile("cp.async.wait_group 1;" ::: "memory")

__device__ __forceinline__ void split2(float a, float b, uint32_t& hi, uint32_t& lo) {
    __nv_bfloat16 ha = __float2bfloat16_rn(a);
    __nv_bfloat16 hb = __float2bfloat16_rn(b);
    __nv_bfloat16 la = __float2bfloat16_rn(a - __bfloat162float(ha));
    __nv_bfloat16 lb = __float2bfloat16_rn(b - __bfloat162float(hb));
    __nv_bfloat162 H; H.x = ha; H.y = hb;
    __nv_bfloat162 L; L.x = la; L.y = lb;
    hi = *reinterpret_cast<uint32_t*>(&H);
    lo = *reinterpret_cast<uint32_t*>(&L);
}

// ---------------------------------------------------------------------------
// Prep A: elementwise fp32 -> bf16 hi/lo (row-major), float4 per thread
// ---------------------------------------------------------------------------
__global__ void split_rows(const float* __restrict__ X, size_t n4,
                           __nv_bfloat16* __restrict__ H,
                           __nv_bfloat16* __restrict__ L) {
    const size_t i = (size_t)blockIdx.x * blockDim.x + threadIdx.x;
    if (i >= n4) return;
    const float4 v = ((const float4*)X)[i];
    uint32_t h01, l01, h23, l23;
    split2(v.x, v.y, h01, l01);
    split2(v.z, v.w, h23, l23);
    ((uint2*)H)[i] = make_uint2(h01, h23);
    ((uint2*)L)[i] = make_uint2(l01, l23);
}

// ---------------------------------------------------------------------------
// Prep W: transpose + split [K x N] fp32 into PACKED swizzled k-16 blocks:
// block (ntile, ktile16) of 4096 B at ((n>>7)*(K/16) + (k>>4))*4096.
// ---------------------------------------------------------------------------
__global__ void transpose_split_pack(const float* __restrict__ W, int K, int N,
                                     __nv_bfloat16* __restrict__ Th,
                                     __nv_bfloat16* __restrict__ Tl) {
    __shared__ float tbuf[32][33];
    const int nb = blockIdx.x * 32, kb = blockIdx.y * 32;
    const int tx = threadIdx.x, ty = threadIdx.y;   // (32, 8)
    #pragma unroll
    for (int j = 0; j < 32; j += 8)
        tbuf[ty + j][tx] = W[(size_t)(kb + ty + j) * N + nb + tx];
    __syncthreads();
    #pragma unroll
    for (int j = 0; j < 32; j += 8) {
        const float x = tbuf[tx][ty + j];            // = W[kb+tx][nb+ty+j]
        const int k = kb + tx;
        const int n = nb + ty + j;
        const __nv_bfloat16 h = __float2bfloat16_rn(x);
        const __nv_bfloat16 l = __float2bfloat16_rn(x - __bfloat162float(h));
        const int lr = n & 127, kc = k & 15, ch = kc >> 3;
        const size_t off = ((size_t)(n >> 7) * (K / 16) + (k >> 4)) * 4096
                         + lr * 32 + ((ch ^ ((lr >> 2) & 1)) << 4) + (kc & 7) * 2;
        *(__nv_bfloat16*)((char*)Th + off) = h;
        *(__nv_bfloat16*)((char*)Tl + off) = l;
    }
}

// ---------------------------------------------------------------------------
// Split-bf16 GEMM layer, 3-stage cp.async pipeline (R6 skeleton, BK=16).
//   GATHER: A rows gathered (m_ids/op_idx) from pre-split row-major bf16,
//           swizzle folded into cp.async destination addresses. Replaces the
//           R6 fp32 LDG->split->STS path (deletes L0's in-loop CVT/FSUB/STS).
//   else:   A from packed tiles, contiguous cp.async (R6-proven).
//   OUTPK:  write packed k-16 blocks for the next layer; else fp32 rows.
// ---------------------------------------------------------------------------
template <int KTOT, bool GATHER, bool OUTPK>
__global__ __launch_bounds__(NTHREADS)
void gemm_mma_kernel(const __nv_bfloat16* __restrict__ Ah,   // GATHER: x_m hi
                     const __nv_bfloat16* __restrict__ Al,
                     const __nv_bfloat16* __restrict__ Oh,   // GATHER: x_op hi
                     const __nv_bfloat16* __restrict__ Ol,
                     const __nv_bfloat16* __restrict__ WTh,
                     const __nv_bfloat16* __restrict__ WTl,
                     const float* __restrict__ bias,
                     const float* __restrict__ W0tail,
                     const float* __restrict__ job_srpt,
                     const float* __restrict__ pt,
                     const int* __restrict__ m_ids,
                     const int* __restrict__ op_idx,
                     const int* __restrict__ job_ids,
                     void* __restrict__ outH, void* __restrict__ outL) {
    extern __shared__ char sm[];
    const uint32_t sbase = smem_u32(sm);
    const int tid = threadIdx.x, wid = tid >> 5, lane = tid & 31;
    const int wm = wid >> 1, wn = wid & 1;
    const int n0 = blockIdx.x * BN, m0 = blockIdx.y * BM;
    constexpr int T = KTOT / BK;
    constexpr int TSW = HDIM / BK;            // L0: k-tile where A switches to x_op

    // B source: packed blocks, contiguous 4 KB per stage per matrix (R6-proven)
    const char* srcBh = (const char*)WTh + (size_t)(n0 >> 7) * T * 4096 + tid * 16;
    const char* srcBl = (const char*)WTl + (size_t)(n0 >> 7) * T * 4096 + tid * 16;

    // A source
    const char *amH = nullptr, *amL = nullptr, *aoH = nullptr, *aoL = nullptr;
    const char *srcAh = nullptr, *srcAl = nullptr;
    const int arow = tid >> 1, ach = tid & 1;       // gather mapping: row, 16B chunk
    const int sb = (arow >> 2) & 1;                 // swizzle bit for this row
    const uint32_t dstA = arow * 32 + ((ach ^ sb) << 4);   // swizzled dest offset
    if constexpr (GATHER) {
        const int m = m0 + arow;
        amH = (const char*)(Ah + (size_t)m_ids[m] * HDIM);
        amL = (const char*)(Al + (size_t)m_ids[m] * HDIM);
        aoH = (const char*)(Oh + (size_t)op_idx[m] * HDIM);
        aoL = (const char*)(Ol + (size_t)op_idx[m] * HDIM);
    } else {
        srcAh = (const char*)Ah + (size_t)(m0 >> 7) * T * 4096 + tid * 16;
        srcAl = (const char*)Al + (size_t)(m0 >> 7) * T * 4096 + tid * 16;
    }

    float acc[2][8][4];
    #pragma unroll
    for (int i = 0; i < 2; ++i)
        #pragma unroll
        for (int j = 0; j < 8; ++j)
            #pragma unroll
            for (int r = 0; r < 4; ++r) acc[i][j][r] = 0.f;

    auto cpStage = [&](int kt, int slot) {
        const uint32_t d = sbase + slot * ST_STRIDE;
        const size_t o = (size_t)kt * 4096;
        cp16(d + ST_BH + tid * 16, srcBh + o);
        cp16(d + ST_BL + tid * 16, srcBl + o);
        if constexpr (GATHER) {
            const char* sh = amH;
            const char* sl = amL;
            int kk = kt;
            if (kt >= TSW) { sh = aoH; sl = aoL; kk = kt - TSW; }
            const size_t so = (size_t)kk * 32 + ach * 16;   // bytes within bf16 row
            cp16(d + ST_AH + dstA, sh + so);
            cp16(d + ST_AL + dstA, sl + so);
        } else {
            cp16(d + ST_AH + tid * 16, srcAh + o);
            cp16(d + ST_AL + tid * 16, srcAl + o);
        }
    };

    // ---- prologue ----
    cpStage(0, 0); CP_COMMIT();
    cpStage(1, 1); CP_COMMIT();

    // per-lane ldmatrix offset (row + swizzled k-chunk) — R6-proven
    const uint32_t lofs = (lane & 15) * 32 + (((lane >> 4) ^ ((lane >> 2) & 1)) << 4);

    for (int t = 0; t < T; ++t) {
        CP_WAIT1();                 // stage t complete (newest group may pend)
        __syncthreads();            // all warps done computing stage t-1
        if (t + 2 < T) cpStage(t + 2, (t + 2) % 3);   // refills slot (t-1)%3
        CP_COMMIT();                // unconditional: keeps wait_group(1) semantics

        const uint32_t st = sbase + (t % 3) * ST_STRIDE;
        uint32_t ah[2][4], al[2][4], bh[4][4], bl[4][4];
        #pragma unroll
        for (int mt = 0; mt < 2; ++mt) {
            const uint32_t ra = st + ST_AH + wm * 1024 + mt * 512 + lofs;
            ldmx4(ah[mt], ra);
            ldmx4(al[mt], ra + (ST_AL - ST_AH));
        }
        #pragma unroll
        for (int p = 0; p < 4; ++p) {
            const uint32_t rb = st + ST_BH + wn * 2048 + p * 512 + lofs;
            ldmx4(bh[p], rb);
            ldmx4(bl[p], rb + (ST_BL - ST_BH));
        }
        #pragma unroll
        for (int mt = 0; mt < 2; ++mt)
            #pragma unroll
            for (int nt = 0; nt < 8; ++nt) {
                const int p = nt >> 1, o = nt & 1;
                mma_bf16(acc[mt][nt], ah[mt], bh[p][o], bh[p][2 + o]);
                mma_bf16(acc[mt][nt], ah[mt], bl[p][o], bl[p][2 + o]);
                mma_bf16(acc[mt][nt], al[mt], bh[p][o], bh[p][2 + o]);
            }
    }

    // ---- epilogue (R6-proven) ----
    const int gq = lane >> 2, tg = lane & 3;
    #pragma unroll
    for (int mt = 0; mt < 2; ++mt) {
        const int lr0 = wm * 32 + mt * 16 + gq;       // local row in [0,128)
        const int lr1 = lr0 + 8;
        const int er0 = m0 + lr0, er1 = m0 + lr1;
        float js0 = 0.f, pv0 = 0.f, js1 = 0.f, pv1 = 0.f;
        if constexpr (GATHER) {
            js0 = job_srpt[job_ids[er0]]; pv0 = pt[er0];
            js1 = job_srpt[job_ids[er1]]; pv1 = pt[er1];
        }
        #pragma unroll
        for (int nt = 0; nt < 8; ++nt) {
            const int nc = n0 + wn * 64 + nt * 8 + tg * 2;
            const float bz0 = bias[nc], bz1 = bias[nc + 1];
            float e00 = 0.f, e01 = 0.f, e10 = 0.f, e11 = 0.f;
            if constexpr (GATHER) {
                const float wa0 = W0tail[nc], wa1 = W0tail[nc + 1];
                const float wb0 = W0tail[HDIM + nc], wb1 = W0tail[HDIM + nc + 1];
                e00 = js0 * wa0 + pv0 * wb0; e01 = js0 * wa1 + pv0 * wb1;
                e10 = js1 * wa0 + pv1 * wb0; e11 = js1 * wa1 + pv1 * wb1;
            }
            float v00 = acc[mt][nt][0] + bz0 + e00;
            float v01 = acc[mt][nt][1] + bz1 + e01;
            float v10 = acc[mt][nt][2] + bz0 + e10;
            float v11 = acc[mt][nt][3] + bz1 + e11;
            v00 = v00 > 0.f ? v00 : 0.01f * v00;
            v01 = v01 > 0.f ? v01 : 0.01f * v01;
            v10 = v10 > 0.f ? v10 : 0.01f * v10;
            v11 = v11 > 0.f ? v11 : 0.01f * v11;
            if constexpr (OUTPK) {
                // packed k-16 blocks for the next layer (its K = HDIM)
                const size_t blk = ((size_t)blockIdx.y * (HDIM / 16) + (nc >> 4)) * 4096;
                const uint32_t sw = ((((nc >> 3) & 1) ^ ((lr0 >> 2) & 1)) << 4);
                const uint32_t o0 = lr0 * 32 + sw + (nc & 7) * 2;
                const uint32_t o1 = lr1 * 32 + sw + (nc & 7) * 2;
                uint32_t h0, l0, h1, l1;
                split2(v00, v01, h0, l0);
                split2(v10, v11, h1, l1);
                *(uint32_t*)((char*)outH + blk + o0) = h0;
                *(uint32_t*)((char*)outL + blk + o0) = l0;
                *(uint32_t*)((char*)outH + blk + o1) = h1;
                *(uint32_t*)((char*)outL + blk + o1) = l1;
            } else {
                float* out = (float*)outH;
                *(float2*)(out + (size_t)er0 * HDIM + nc) = make_float2(v00, v01);
                *(float2*)(out + (size_t)er1 * HDIM + nc) = make_float2(v10, v11);
            }
        }
    }
}

// ---------------------------------------------------------------------------
// Final layer GEMV: scores[m] = h[m,:] . W3 + b3
// ---------------------------------------------------------------------------
__global__ void gemv_kernel(const float* __restrict__ hbuf,
                            const float* __restrict__ W3,
                            const float* __restrict__ b3,
                            float* __restrict__ scores) {
    const int gw = (int)((blockIdx.x * blockDim.x + threadIdx.x) >> 5);
    const int lane = threadIdx.x & 31;
    if (gw >= NAVAIL) return;
    const float4* hr = (const float4*)(hbuf + (size_t)gw * HDIM);
    const float4* wr = (const float4*)W3;
    float s = 0.f;
    #pragma unroll 4
    for (int i = lane; i < HDIM / 4; i += 32) {
        const float4 a = hr[i];
        const float4 w = wr[i];
        s += a.x * w.x + a.y * w.y + a.z * w.z + a.w * w.w;
    }
    #pragma unroll
    for (int off = 16; off > 0; off >>= 1)
        s += __shfl_down_sync(0xffffffffu, s, off);
    if (lane == 0) scores[gw] = s + b3[0];
}

// ---------------------------------------------------------------------------
// Softmax + argmax (first-max semantics), single block.
// ---------------------------------------------------------------------------
__global__ void softmax_kernel(const float* __restrict__ scores,
                               float* __restrict__ out, int out_size) {
    const int tid = threadIdx.x;
    const int lane = tid & 31;
    const int wid = tid >> 5;
    __shared__ float red_f[32];
    __shared__ int   red_i[32];
    __shared__ float red_s[32];

    float bmax = -INFINITY;
    int bidx = 0x7fffffff;
    for (int i = tid; i < NAVAIL; i += 1024) {
        const float v = scores[i];
        if (v > bmax) { bmax = v; bidx = i; }
    }
    #pragma unroll
    for (int off = 16; off > 0; off >>= 1) {
        const float om = __shfl_down_sync(0xffffffffu, bmax, off);
        const int oi = __shfl_down_sync(0xffffffffu, bidx, off);
        if (om > bmax || (om == bmax && oi < bidx)) { bmax = om; bidx = oi; }
    }
    if (lane == 0) { red_f[wid] = bmax; red_i[wid] = bidx; }
    __syncthreads();
    if (tid < 32) {
        bmax = red_f[tid];
        bidx = red_i[tid];
        #pragma unroll
        for (int off = 16; off > 0; off >>= 1) {
            const float om = __shfl_down_sync(0xffffffffu, bmax, off);
            const int oi = __shfl_down_sync(0xffffffffu, bidx, off);
            if (om > bmax || (om == bmax && oi < bidx)) { bmax = om; bidx = oi; }
        }
        if (tid == 0) { red_f[0] = bmax; red_i[0] = bidx; }
    }
    __syncthreads();
    const float gmax = red_f[0];
    const int gidx = red_i[0];

    float s = 0.f;
    for (int i = tid; i < NAVAIL; i += 1024) {
        const float e = expf(scores[i] - gmax);
        out[i] = e;
        s += e;
    }
    #pragma unroll
    for (int off = 16; off > 0; off >>= 1)
        s += __shfl_down_sync(0xffffffffu, s, off);
    if (lane == 0) red_s[wid] = s;
    __syncthreads();
    if (tid < 32) {
        s = red_s[tid];
        #pragma unroll
        for (int off = 16; off > 0; off >>= 1)
            s += __shfl_down_sync(0xffffffffu, s, off);
        if (tid == 0) red_s[0] = s;
    }
    __syncthreads();
    const float inv = 1.0f / red_s[0];
    for (int i = tid; i < NAVAIL; i += 1024)
        out[i] *= inv;
    for (int i = NAVAIL + tid; i < out_size; i += 1024)
        out[i] = (float)gidx;
}

// ---------------------------------------------------------------------------
// Launch. inputs: x_m, x_op, job_srpt, pt, W0, b0, W1, b1, W2, b2, W3, b3,
//                 m_ids, op_idx, job_ids
// Host API surface: cudaGetSymbolAddress + launches only. NO cudaFuncSetAttribute
// (0/8 container attempts ever passed with it; suspected _HX_ENFORCE
// "device limits changed" guard). Dynamic smem stays at the 48 KB default cap.
// ---------------------------------------------------------------------------
extern "C" void kernel_launch(void* const* d_in, const int* in_sizes, int n_in,
                              void* d_out, int out_size) {
    const float* x_m      = (const float*)d_in[0];
    const float* x_op     = (const float*)d_in[1];
    const float* job_srpt = (const float*)d_in[2];
    const float* pt       = (const float*)d_in[3];
    const float* W0       = (const float*)d_in[4];
    const float* b0       = (const float*)d_in[5];
    const float* W1       = (const float*)d_in[6];
    const float* b1       = (const float*)d_in[7];
    const float* W2       = (const float*)d_in[8];
    const float* b2       = (const float*)d_in[9];
    const float* W3       = (const float*)d_in[10];
    const float* b3       = (const float*)d_in[11];
    const int*   m_ids    = (const int*)d_in[12];
    const int*   op_idx   = (const int*)d_in[13];
    const int*   job_ids  = (const int*)d_in[14];
    float* out = (float*)d_out;

    float *h2, *sc;
    __nv_bfloat16 *xmh, *xml, *xoh, *xol, *a0h, *a0l, *a1h, *a1l;
    __nv_bfloat16 *w0h, *w0l, *w1h, *w1l, *w2h, *w2l;
    cudaGetSymbolAddress((void**)&h2, g_h2);
    cudaGetSymbolAddress((void**)&sc, g_scores);
    cudaGetSymbolAddress((void**)&xmh, g_xmh);
    cudaGetSymbolAddress((void**)&xml, g_xml);
    cudaGetSymbolAddress((void**)&xoh, g_xoh);
    cudaGetSymbolAddress((void**)&xol, g_xol);
    cudaGetSymbolAddress((void**)&a0h, g_a0h);
    cudaGetSymbolAddress((void**)&a0l, g_a0l);
    cudaGetSymbolAddress((void**)&a1h, g_a1h);
    cudaGetSymbolAddress((void**)&a1l, g_a1l);
    cudaGetSymbolAddress((void**)&w0h, g_wt0h);
    cudaGetSymbolAddress((void**)&w0l, g_wt0l);
    cudaGetSymbolAddress((void**)&w1h, g_wt1h);
    cudaGetSymbolAddress((void**)&w1l, g_wt1l);
    cudaGetSymbolAddress((void**)&w2h, g_wt2h);
    cudaGetSymbolAddress((void**)&w2l, g_wt2l);

    // prep: split activations + pack weights (off critical path, ~60us)
    {
        const size_t nm4 = (size_t)NM * HDIM / 4;
        const size_t no4 = (size_t)NOP * HDIM / 4;
        split_rows<<<(int)((nm4 + 255) / 256), 256>>>(x_m, nm4, xmh, xml);
        split_rows<<<(int)((no4 + 255) / 256), 256>>>(x_op, no4, xoh, xol);
        dim3 thr(32, 8);
        transpose_split_pack<<<dim3(HDIM / 32, KFULL / 32), thr>>>(W0, KFULL, HDIM, w0h, w0l);
        transpose_split_pack<<<dim3(HDIM / 32, HDIM / 32), thr>>>(W1, HDIM, HDIM, w1h, w1l);
        transpose_split_pack<<<dim3(HDIM / 32, HDIM / 32), thr>>>(W2, HDIM, HDIM, w2h, w2l);
    }

    const dim3 grid(HDIM / BN, NAVAIL / BM);   // (8, 256)
    const float* W0tail = W0 + (size_t)KFULL * HDIM;   // rows 2048, 2049

    gemm_mma_kernel<KFULL, true, true><<<grid, NTHREADS, SMEM_BYTES>>>(
        xmh, xml, xoh, xol, w0h, w0l, b0, W0tail, job_srpt, pt,
        m_ids, op_idx, job_ids, a0h, a0l);
    gemm_mma_kernel<HDIM, false, true><<<grid, NTHREADS, SMEM_BYTES>>>(
        a0h, a0l, nullptr, nullptr, w1h, w1l, b1, nullptr, nullptr, nullptr,
        nullptr, nullptr, nullptr, a1h, a1l);
    gemm_mma_kernel<HDIM, false, false><<<grid, NTHREADS, SMEM_BYTES>>>(
        a1h, a1l, nullptr, nullptr, w2h, w2l, b2, nullptr, nullptr, nullptr,
        nullptr, nullptr, nullptr, h2, nullptr);

    gemv_kernel<<<NAVAIL / 8, 256>>>(h2, W3, b3, sc);
    softmax_kernel<<<1, 1024>>>(sc, out, out_size);
}

// round 13
// speedup vs baseline: 1.1758x; 1.0235x over previous
#include <cuda_runtime.h>
#include <cuda_bf16.h>
#include <cstdint>
#include <math.h>

// ---------------------------------------------------------------------------
// Problem constants
// ---------------------------------------------------------------------------
#define HDIM   1024
#define NAVAIL 32768
#define KFULL  2048      // GEMM0 K (the +2 scalar features handled in epilogue)
#define NOP    40000     // x_op rows
#define NM     64        // x_m rows
#define NBX    (HDIM / 128)   // 8 N-tiles -> 8 partial-score slots

// GEMM tiling (mma.sync m16n8k16 bf16)
#define BM 128
#define BN 128
#define BK 16
#define NTHREADS 256     // 8 warps: 4 (M) x 2 (N)

// Packed tile format (R6-proven): per k-16 block of 4096 B, row stride 32 B:
//   byte(r, ch, c) = r*32 + ((ch ^ ((r>>2)&1))<<4) + c*2   (ch = 8-col chunk)
#define ST_AH 0
#define ST_AL 4096
#define ST_BH 8192
#define ST_BL 12288
#define ST_STRIDE 16384
#define SMEM_BYTES (3 * ST_STRIDE)   // 49152 = default cap: NO attr call (hard rule)

// ---------------------------------------------------------------------------
// Device scratch (no runtime allocation allowed)
// ---------------------------------------------------------------------------
__device__ float g_scores[NAVAIL];
__device__ float g_part[(size_t)NBX * NAVAIL];                // per-bx partial dots
__device__ __nv_bfloat16 g_xmh[(size_t)NM * HDIM];            // x_m split (row-major)
__device__ __nv_bfloat16 g_xml[(size_t)NM * HDIM];
__device__ __nv_bfloat16 g_xoh[(size_t)NOP * HDIM];           // x_op split (row-major)
__device__ __nv_bfloat16 g_xol[(size_t)NOP * HDIM];
__device__ __nv_bfloat16 g_a0h[(size_t)NAVAIL * HDIM];        // layer outs (PACKED tiles)
__device__ __nv_bfloat16 g_a0l[(size_t)NAVAIL * HDIM];
__device__ __nv_bfloat16 g_a1h[(size_t)NAVAIL * HDIM];
__device__ __nv_bfloat16 g_a1l[(size_t)NAVAIL * HDIM];
__device__ __nv_bfloat16 g_wt0h[(size_t)HDIM * KFULL];        // W^T packed tiles
__device__ __nv_bfloat16 g_wt0l[(size_t)HDIM * KFULL];
__device__ __nv_bfloat16 g_wt1h[(size_t)HDIM * HDIM];
__device__ __nv_bfloat16 g_wt1l[(size_t)HDIM * HDIM];
__device__ __nv_bfloat16 g_wt2h[(size_t)HDIM * HDIM];
__device__ __nv_bfloat16 g_wt2l[(size_t)HDIM * HDIM];

// ---------------------------------------------------------------------------
// Helpers (all sm_80-era PTX; nothing arch-accelerated)
// ---------------------------------------------------------------------------
__device__ __forceinline__ uint32_t smem_u32(const void* p) {
    uint32_t a;
    asm("{ .reg .u64 t; cvta.to.shared.u64 t, %1; cvt.u32.u64 %0, t; }"
        : "=r"(a) : "l"(p));
    return a;
}
__device__ __forceinline__ void ldmx4(uint32_t* r, uint32_t addr) {
    asm volatile("ldmatrix.sync.aligned.m8n8.x4.shared.b16 {%0,%1,%2,%3}, [%4];"
                 : "=r"(r[0]), "=r"(r[1]), "=r"(r[2]), "=r"(r[3]) : "r"(addr));
}
__device__ __forceinline__ void mma_bf16(float* d, const uint32_t* a,
                                         uint32_t b0, uint32_t b1) {
    asm volatile("mma.sync.aligned.m16n8k16.row.col.f32.bf16.bf16.f32 "
                 "{%0,%1,%2,%3}, {%4,%5,%6,%7}, {%8,%9}, {%0,%1,%2,%3};"
                 : "+f"(d[0]), "+f"(d[1]), "+f"(d[2]), "+f"(d[3])
                 : "r"(a[0]), "r"(a[1]), "r"(a[2]), "r"(a[3]), "r"(b0), "r"(b1));
}
__device__ __forceinline__ void cp16(uint32_t dst, const void* src) {
    asm volatile("cp.async.cg.shared.global [%0], [%1], 16;"
                 :: "r"(dst), "l"(src) : "memory");
}
#define CP_COMMIT() asm volatile("cp.async.commit_group;" ::: "memory")
#define CP_WAIT1()  asm volatile("cp.async.wait_group 1;" ::: "memory")

__device__ __forceinline__ void split2(float a, float b, uint32_t& hi, uint32_t& lo) {
    __nv_bfloat16 ha = __float2bfloat16_rn(a);
    __nv_bfloat16 hb = __float2bfloat16_rn(b);
    __nv_bfloat16 la = __float2bfloat16_rn(a - __bfloat162float(ha));
    __nv_bfloat16 lb = __float2bfloat16_rn(b - __bfloat162float(hb));
    __nv_bfloat162 H; H.x = ha; H.y = hb;
    __nv_bfloat162 L; L.x = la; L.y = lb;
    hi = *reinterpret_cast<uint32_t*>(&H);
    lo = *reinterpret_cast<uint32_t*>(&L);
}

// ---------------------------------------------------------------------------
// Prep A: elementwise fp32 -> bf16 hi/lo (row-major), float4 per thread
// ---------------------------------------------------------------------------
__global__ void split_rows(const float* __restrict__ X, size_t n4,
                           __nv_bfloat16* __restrict__ H,
                           __nv_bfloat16* __restrict__ L) {
    const size_t i = (size_t)blockIdx.x * blockDim.x + threadIdx.x;
    if (i >= n4) return;
    const float4 v = ((const float4*)X)[i];
    uint32_t h01, l01, h23, l23;
    split2(v.x, v.y, h01, l01);
    split2(v.z, v.w, h23, l23);
    ((uint2*)H)[i] = make_uint2(h01, h23);
    ((uint2*)L)[i] = make_uint2(l01, l23);
}

// ---------------------------------------------------------------------------
// Prep W: transpose + split [K x N] fp32 into PACKED swizzled k-16 blocks:
// block (ntile, ktile16) of 4096 B at ((n>>7)*(K/16) + (k>>4))*4096.
// ---------------------------------------------------------------------------
__global__ void transpose_split_pack(const float* __restrict__ W, int K, int N,
                                     __nv_bfloat16* __restrict__ Th,
                                     __nv_bfloat16* __restrict__ Tl) {
    __shared__ float tbuf[32][33];
    const int nb = blockIdx.x * 32, kb = blockIdx.y * 32;
    const int tx = threadIdx.x, ty = threadIdx.y;   // (32, 8)
    #pragma unroll
    for (int j = 0; j < 32; j += 8)
        tbuf[ty + j][tx] = W[(size_t)(kb + ty + j) * N + nb + tx];
    __syncthreads();
    #pragma unroll
    for (int j = 0; j < 32; j += 8) {
        const float x = tbuf[tx][ty + j];            // = W[kb+tx][nb+ty+j]
        const int k = kb + tx;
        const int n = nb + ty + j;
        const __nv_bfloat16 h = __float2bfloat16_rn(x);
        const __nv_bfloat16 l = __float2bfloat16_rn(x - __bfloat162float(h));
        const int lr = n & 127, kc = k & 15, ch = kc >> 3;
        const size_t off = ((size_t)(n >> 7) * (K / 16) + (k >> 4)) * 4096
                         + lr * 32 + ((ch ^ ((lr >> 2) & 1)) << 4) + (kc & 7) * 2;
        *(__nv_bfloat16*)((char*)Th + off) = h;
        *(__nv_bfloat16*)((char*)Tl + off) = l;
    }
}

// ---------------------------------------------------------------------------
// Split-bf16 GEMM layer, 3-stage cp.async pipeline (R11-proven skeleton).
//   GATHER: A rows gathered (m_ids/op_idx) from pre-split row-major bf16.
//   else:   A from packed tiles, contiguous cp.async.
//   OUTPK:  write packed k-16 blocks for the next layer.
//   !OUTPK: FUSED FINAL LAYER: dot the output block with W3 in-register,
//           reduce to per-(bx, row) partial scores (deterministic: exactly
//           two commutative smem-atomic contributions per row, then fixed-
//           order global reduce in a separate kernel). No h2, no gemv.
// ---------------------------------------------------------------------------
template <int KTOT, bool GATHER, bool OUTPK>
__global__ __launch_bounds__(NTHREADS)
void gemm_mma_kernel(const __nv_bfloat16* __restrict__ Ah,   // GATHER: x_m hi
                     const __nv_bfloat16* __restrict__ Al,
                     const __nv_bfloat16* __restrict__ Oh,   // GATHER: x_op hi
                     const __nv_bfloat16* __restrict__ Ol,
                     const __nv_bfloat16* __restrict__ WTh,
                     const __nv_bfloat16* __restrict__ WTl,
                     const float* __restrict__ bias,
                     const float* __restrict__ W0tail,
                     const float* __restrict__ W3,          // !OUTPK only
                     const float* __restrict__ job_srpt,
                     const float* __restrict__ pt,
                     const int* __restrict__ m_ids,
                     const int* __restrict__ op_idx,
                     const int* __restrict__ job_ids,
                     void* __restrict__ outH, void* __restrict__ outL) {
    extern __shared__ char sm[];
    const uint32_t sbase = smem_u32(sm);
    const int tid = threadIdx.x, wid = tid >> 5, lane = tid & 31;
    const int wm = wid >> 1, wn = wid & 1;
    const int n0 = blockIdx.x * BN, m0 = blockIdx.y * BM;
    constexpr int T = KTOT / BK;
    constexpr int TSW = HDIM / BK;            // L0: k-tile where A switches to x_op

    // B source: packed blocks, contiguous 4 KB per stage per matrix
    const char* srcBh = (const char*)WTh + (size_t)(n0 >> 7) * T * 4096 + tid * 16;
    const char* srcBl = (const char*)WTl + (size_t)(n0 >> 7) * T * 4096 + tid * 16;

    // A source
    const char *amH = nullptr, *amL = nullptr, *aoH = nullptr, *aoL = nullptr;
    const char *srcAh = nullptr, *srcAl = nullptr;
    const int arow = tid >> 1, ach = tid & 1;       // gather mapping: row, 16B chunk
    const int sb = (arow >> 2) & 1;                 // swizzle bit for this row
    const uint32_t dstA = arow * 32 + ((ach ^ sb) << 4);   // swizzled dest offset
    if constexpr (GATHER) {
        const int m = m0 + arow;
        amH = (const char*)(Ah + (size_t)m_ids[m] * HDIM);
        amL = (const char*)(Al + (size_t)m_ids[m] * HDIM);
        aoH = (const char*)(Oh + (size_t)op_idx[m] * HDIM);
        aoL = (const char*)(Ol + (size_t)op_idx[m] * HDIM);
    } else {
        srcAh = (const char*)Ah + (size_t)(m0 >> 7) * T * 4096 + tid * 16;
        srcAl = (const char*)Al + (size_t)(m0 >> 7) * T * 4096 + tid * 16;
    }

    float acc[2][8][4];
    #pragma unroll
    for (int i = 0; i < 2; ++i)
        #pragma unroll
        for (int j = 0; j < 8; ++j)
            #pragma unroll
            for (int r = 0; r < 4; ++r) acc[i][j][r] = 0.f;

    auto cpStage = [&](int kt, int slot) {
        const uint32_t d = sbase + slot * ST_STRIDE;
        const size_t o = (size_t)kt * 4096;
        cp16(d + ST_BH + tid * 16, srcBh + o);
        cp16(d + ST_BL + tid * 16, srcBl + o);
        if constexpr (GATHER) {
            const char* sh = amH;
            const char* sl = amL;
            int kk = kt;
            if (kt >= TSW) { sh = aoH; sl = aoL; kk = kt - TSW; }
            const size_t so = (size_t)kk * 32 + ach * 16;   // bytes within bf16 row
            cp16(d + ST_AH + dstA, sh + so);
            cp16(d + ST_AL + dstA, sl + so);
        } else {
            cp16(d + ST_AH + tid * 16, srcAh + o);
            cp16(d + ST_AL + tid * 16, srcAl + o);
        }
    };

    // ---- prologue ----
    cpStage(0, 0); CP_COMMIT();
    cpStage(1, 1); CP_COMMIT();

    // per-lane ldmatrix offset (row + swizzled k-chunk)
    const uint32_t lofs = (lane & 15) * 32 + (((lane >> 4) ^ ((lane >> 2) & 1)) << 4);

    for (int t = 0; t < T; ++t) {
        CP_WAIT1();                 // stage t complete (newest group may pend)
        __syncthreads();            // all warps done computing stage t-1
        if (t + 2 < T) cpStage(t + 2, (t + 2) % 3);   // refills slot (t-1)%3
        CP_COMMIT();                // unconditional: keeps wait_group(1) semantics

        const uint32_t st = sbase + (t % 3) * ST_STRIDE;
        uint32_t ah[2][4], al[2][4], bh[4][4], bl[4][4];
        #pragma unroll
        for (int mt = 0; mt < 2; ++mt) {
            const uint32_t ra = st + ST_AH + wm * 1024 + mt * 512 + lofs;
            ldmx4(ah[mt], ra);
            ldmx4(al[mt], ra + (ST_AL - ST_AH));
        }
        #pragma unroll
        for (int p = 0; p < 4; ++p) {
            const uint32_t rb = st + ST_BH + wn * 2048 + p * 512 + lofs;
            ldmx4(bh[p], rb);
            ldmx4(bl[p], rb + (ST_BL - ST_BH));
        }
        #pragma unroll
        for (int mt = 0; mt < 2; ++mt)
            #pragma unroll
            for (int nt = 0; nt < 8; ++nt) {
                const int p = nt >> 1, o = nt & 1;
                mma_bf16(acc[mt][nt], ah[mt], bh[p][o], bh[p][2 + o]);
                mma_bf16(acc[mt][nt], ah[mt], bl[p][o], bl[p][2 + o]);
                mma_bf16(acc[mt][nt], al[mt], bh[p][o], bh[p][2 + o]);
            }
    }

    // ---- epilogue ----
    const int gq = lane >> 2, tg = lane & 3;

    float* sPart = (float*)sm;      // aliases stage 0 (free after loop + sync)
    if constexpr (!OUTPK) {
        __syncthreads();            // all warps out of the main loop (smem reuse)
        if (tid < BM) sPart[tid] = 0.f;
        __syncthreads();
    }

    #pragma unroll
    for (int mt = 0; mt < 2; ++mt) {
        const int lr0 = wm * 32 + mt * 16 + gq;       // local row in [0,128)
        const int lr1 = lr0 + 8;
        const int er0 = m0 + lr0, er1 = m0 + lr1;
        float js0 = 0.f, pv0 = 0.f, js1 = 0.f, pv1 = 0.f;
        if constexpr (GATHER) {
            js0 = job_srpt[job_ids[er0]]; pv0 = pt[er0];
            js1 = job_srpt[job_ids[er1]]; pv1 = pt[er1];
        }
        float p0 = 0.f, p1 = 0.f;                     // fused-dot partials
        #pragma unroll
        for (int nt = 0; nt < 8; ++nt) {
            const int nc = n0 + wn * 64 + nt * 8 + tg * 2;
            const float bz0 = bias[nc], bz1 = bias[nc + 1];
            float e00 = 0.f, e01 = 0.f, e10 = 0.f, e11 = 0.f;
            if constexpr (GATHER) {
                const float wa0 = W0tail[nc], wa1 = W0tail[nc + 1];
                const float wb0 = W0tail[HDIM + nc], wb1 = W0tail[HDIM + nc + 1];
                e00 = js0 * wa0 + pv0 * wb0; e01 = js0 * wa1 + pv0 * wb1;
                e10 = js1 * wa0 + pv1 * wb0; e11 = js1 * wa1 + pv1 * wb1;
            }
            float v00 = acc[mt][nt][0] + bz0 + e00;
            float v01 = acc[mt][nt][1] + bz1 + e01;
            float v10 = acc[mt][nt][2] + bz0 + e10;
            float v11 = acc[mt][nt][3] + bz1 + e11;
            v00 = v00 > 0.f ? v00 : 0.01f * v00;
            v01 = v01 > 0.f ? v01 : 0.01f * v01;
            v10 = v10 > 0.f ? v10 : 0.01f * v10;
            v11 = v11 > 0.f ? v11 : 0.01f * v11;
            if constexpr (OUTPK) {
                // packed k-16 blocks for the next layer (its K = HDIM)
                const size_t blk = ((size_t)blockIdx.y * (HDIM / 16) + (nc >> 4)) * 4096;
                const uint32_t sw = ((((nc >> 3) & 1) ^ ((lr0 >> 2) & 1)) << 4);
                const uint32_t o0 = lr0 * 32 + sw + (nc & 7) * 2;
                const uint32_t o1 = lr1 * 32 + sw + (nc & 7) * 2;
                uint32_t h0, l0, h1, l1;
                split2(v00, v01, h0, l0);
                split2(v10, v11, h1, l1);
                *(uint32_t*)((char*)outH + blk + o0) = h0;
                *(uint32_t*)((char*)outL + blk + o0) = l0;
                *(uint32_t*)((char*)outH + blk + o1) = h1;
                *(uint32_t*)((char*)outL + blk + o1) = l1;
            } else {
                const float w0 = W3[nc], w1 = W3[nc + 1];
                p0 += v00 * w0 + v01 * w1;
                p1 += v10 * w0 + v11 * w1;
            }
        }
        if constexpr (!OUTPK) {
            // reduce across the 4 tg lanes of this quad (same rows)
            p0 += __shfl_xor_sync(0xffffffffu, p0, 1);
            p0 += __shfl_xor_sync(0xffffffffu, p0, 2);
            p1 += __shfl_xor_sync(0xffffffffu, p1, 1);
            p1 += __shfl_xor_sync(0xffffffffu, p1, 2);
            if (tg == 0) {
                // exactly 2 contributions per row (wn=0,1): commutative -> deterministic
                atomicAdd(&sPart[lr0], p0);
                atomicAdd(&sPart[lr1], p1);
            }
        }
    }

    if constexpr (!OUTPK) {
        __syncthreads();
        float* part = (float*)outH;   // g_part
        if (tid < BM)
            part[(size_t)blockIdx.x * NAVAIL + m0 + tid] = sPart[tid];
    }
}

// ---------------------------------------------------------------------------
// Deterministic 8-way reduce of per-bx partial dots -> scores (b3 dropped:
// softmax/argmax are invariant to the constant shift).
// ---------------------------------------------------------------------------
__global__ void reduce_scores(const float* __restrict__ part,
                              float* __restrict__ scores) {
    const int m = blockIdx.x * blockDim.x + threadIdx.x;
    if (m >= NAVAIL) return;
    float s = 0.f;
    #pragma unroll
    for (int b = 0; b < NBX; ++b)
        s += part[(size_t)b * NAVAIL + m];
    scores[m] = s;
}

// ---------------------------------------------------------------------------
// Softmax + argmax (first-max semantics), single block.
// ---------------------------------------------------------------------------
__global__ void softmax_kernel(const float* __restrict__ scores,
                               float* __restrict__ out, int out_size) {
    const int tid = threadIdx.x;
    const int lane = tid & 31;
    const int wid = tid >> 5;
    __shared__ float red_f[32];
    __shared__ int   red_i[32];
    __shared__ float red_s[32];

    float bmax = -INFINITY;
    int bidx = 0x7fffffff;
    for (int i = tid; i < NAVAIL; i += 1024) {
        const float v = scores[i];
        if (v > bmax) { bmax = v; bidx = i; }
    }
    #pragma unroll
    for (int off = 16; off > 0; off >>= 1) {
        const float om = __shfl_down_sync(0xffffffffu, bmax, off);
        const int oi = __shfl_down_sync(0xffffffffu, bidx, off);
        if (om > bmax || (om == bmax && oi < bidx)) { bmax = om; bidx = oi; }
    }
    if (lane == 0) { red_f[wid] = bmax; red_i[wid] = bidx; }
    __syncthreads();
    if (tid < 32) {
        bmax = red_f[tid];
        bidx = red_i[tid];
        #pragma unroll
        for (int off = 16; off > 0; off >>= 1) {
            const float om = __shfl_down_sync(0xffffffffu, bmax, off);
            const int oi = __shfl_down_sync(0xffffffffu, bidx, off);
            if (om > bmax || (om == bmax && oi < bidx)) { bmax = om; bidx = oi; }
        }
        if (tid == 0) { red_f[0] = bmax; red_i[0] = bidx; }
    }
    __syncthreads();
    const float gmax = red_f[0];
    const int gidx = red_i[0];

    float s = 0.f;
    for (int i = tid; i < NAVAIL; i += 1024) {
        const float e = expf(scores[i] - gmax);
        out[i] = e;
        s += e;
    }
    #pragma unroll
    for (int off = 16; off > 0; off >>= 1)
        s += __shfl_down_sync(0xffffffffu, s, off);
    if (lane == 0) red_s[wid] = s;
    __syncthreads();
    if (tid < 32) {
        s = red_s[tid];
        #pragma unroll
        for (int off = 16; off > 0; off >>= 1)
            s += __shfl_down_sync(0xffffffffu, s, off);
        if (tid == 0) red_s[0] = s;
    }
    __syncthreads();
    const float inv = 1.0f / red_s[0];
    for (int i = tid; i < NAVAIL; i += 1024)
        out[i] *= inv;
    for (int i = NAVAIL + tid; i < out_size; i += 1024)
        out[i] = (float)gidx;
}

// ---------------------------------------------------------------------------
// Launch. inputs: x_m, x_op, job_srpt, pt, W0, b0, W1, b1, W2, b2, W3, b3,
//                 m_ids, op_idx, job_ids
// Host API surface: cudaGetSymbolAddress + launches only (NO attr calls;
// 0/8 container attempts ever passed with cudaFuncSetAttribute).
// ---------------------------------------------------------------------------
extern "C" void kernel_launch(void* const* d_in, const int* in_sizes, int n_in,
                              void* d_out, int out_size) {
    const float* x_m      = (const float*)d_in[0];
    const float* x_op     = (const float*)d_in[1];
    const float* job_srpt = (const float*)d_in[2];
    const float* pt       = (const float*)d_in[3];
    const float* W0       = (const float*)d_in[4];
    const float* b0       = (const float*)d_in[5];
    const float* W1       = (const float*)d_in[6];
    const float* b1       = (const float*)d_in[7];
    const float* W2       = (const float*)d_in[8];
    const float* b2       = (const float*)d_in[9];
    const float* W3       = (const float*)d_in[10];
    const int*   m_ids    = (const int*)d_in[12];
    const int*   op_idx   = (const int*)d_in[13];
    const int*   job_ids  = (const int*)d_in[14];
    float* out = (float*)d_out;

    float *sc, *partp;
    __nv_bfloat16 *xmh, *xml, *xoh, *xol, *a0h, *a0l, *a1h, *a1l;
    __nv_bfloat16 *w0h, *w0l, *w1h, *w1l, *w2h, *w2l;
    cudaGetSymbolAddress((void**)&sc, g_scores);
    cudaGetSymbolAddress((void**)&partp, g_part);
    cudaGetSymbolAddress((void**)&xmh, g_xmh);
    cudaGetSymbolAddress((void**)&xml, g_xml);
    cudaGetSymbolAddress((void**)&xoh, g_xoh);
    cudaGetSymbolAddress((void**)&xol, g_xol);
    cudaGetSymbolAddress((void**)&a0h, g_a0h);
    cudaGetSymbolAddress((void**)&a0l, g_a0l);
    cudaGetSymbolAddress((void**)&a1h, g_a1h);
    cudaGetSymbolAddress((void**)&a1l, g_a1l);
    cudaGetSymbolAddress((void**)&w0h, g_wt0h);
    cudaGetSymbolAddress((void**)&w0l, g_wt0l);
    cudaGetSymbolAddress((void**)&w1h, g_wt1h);
    cudaGetSymbolAddress((void**)&w1l, g_wt1l);
    cudaGetSymbolAddress((void**)&w2h, g_wt2h);
    cudaGetSymbolAddress((void**)&w2l, g_wt2l);

    // prep: split activations + pack weights (off critical path)
    {
        const size_t nm4 = (size_t)NM * HDIM / 4;
        const size_t no4 = (size_t)NOP * HDIM / 4;
        split_rows<<<(int)((nm4 + 255) / 256), 256>>>(x_m, nm4, xmh, xml);
        split_rows<<<(int)((no4 + 255) / 256), 256>>>(x_op, no4, xoh, xol);
        dim3 thr(32, 8);
        transpose_split_pack<<<dim3(HDIM / 32, KFULL / 32), thr>>>(W0, KFULL, HDIM, w0h, w0l);
        transpose_split_pack<<<dim3(HDIM / 32, HDIM / 32), thr>>>(W1, HDIM, HDIM, w1h, w1l);
        transpose_split_pack<<<dim3(HDIM / 32, HDIM / 32), thr>>>(W2, HDIM, HDIM, w2h, w2l);
    }

    const dim3 grid(HDIM / BN, NAVAIL / BM);   // (8, 256)
    const float* W0tail = W0 + (size_t)KFULL * HDIM;   // rows 2048, 2049

    gemm_mma_kernel<KFULL, true, true><<<grid, NTHREADS, SMEM_BYTES>>>(
        xmh, xml, xoh, xol, w0h, w0l, b0, W0tail, nullptr, job_srpt, pt,
        m_ids, op_idx, job_ids, a0h, a0l);
    gemm_mma_kernel<HDIM, false, true><<<grid, NTHREADS, SMEM_BYTES>>>(
        a0h, a0l, nullptr, nullptr, w1h, w1l, b1, nullptr, nullptr, nullptr,
        nullptr, nullptr, nullptr, nullptr, a1h, a1l);
    // final layer: fused h2 dot W3 -> per-bx partial scores (no h2, no gemv;
    // b3 dropped: softmax/argmax invariant to constant score shift)
    gemm_mma_kernel<HDIM, false, false><<<grid, NTHREADS, SMEM_BYTES>>>(
        a1h, a1l, nullptr, nullptr, w2h, w2l, b2, nullptr, W3, nullptr,
        nullptr, nullptr, nullptr, nullptr, partp, nullptr);

    reduce_scores<<<NAVAIL / 256, 256>>>(partp, sc);
    softmax_kernel<<<1, 1024>>>(sc, out, out_size);
}

// round 16
// speedup vs baseline: 1.4701x; 1.2503x over previous
#include <cuda_runtime.h>
#include <cuda_bf16.h>
#include <cstdint>
#include <math.h>

// ---------------------------------------------------------------------------
// Problem constants
// ---------------------------------------------------------------------------
#define HDIM   1024
#define NAVAIL 32768
#define NOP    40000     // x_op rows
#define NM     64        // x_m rows
#define NBX    (HDIM / 128)   // 8 N-tiles -> 8 partial-score slots

// GEMM tiling (mma.sync m16n8k16 bf16)
#define BM 128
#define BN 128
#define BK 16
#define NTHREADS 256     // 8 warps: 4 (M) x 2 (N)

// Packed tile format (R6-proven): per k-16 block of 4096 B, row stride 32 B:
//   byte(r, ch, c) = r*32 + ((ch ^ ((r>>2)&1))<<4) + c*2   (ch = 8-col chunk)
#define ST_AH 0
#define ST_AL 4096
#define ST_BH 8192
#define ST_BL 12288
#define ST_STRIDE 16384
#define SMEM_BYTES (3 * ST_STRIDE)   // 49152 = default cap: NO attr call (hard rule)

// ---------------------------------------------------------------------------
// Device scratch (no runtime allocation allowed)
// ---------------------------------------------------------------------------
__device__ float g_scores[NAVAIL];
__device__ float g_part[(size_t)NBX * NAVAIL];                // per-bx partial dots
__device__ float g_xmp[(size_t)NM * HDIM];                    // x_m @ W0[0:1024] (fp32)
__device__ __nv_bfloat16 g_xoh[(size_t)NOP * HDIM];           // x_op split (row-major)
__device__ __nv_bfloat16 g_xol[(size_t)NOP * HDIM];
__device__ __nv_bfloat16 g_a0h[(size_t)NAVAIL * HDIM];        // layer outs (PACKED tiles)
__device__ __nv_bfloat16 g_a0l[(size_t)NAVAIL * HDIM];
__device__ __nv_bfloat16 g_a1h[(size_t)NAVAIL * HDIM];
__device__ __nv_bfloat16 g_a1l[(size_t)NAVAIL * HDIM];
__device__ __nv_bfloat16 g_wt0h[(size_t)HDIM * HDIM];         // W0[1024:2048]^T packed
__device__ __nv_bfloat16 g_wt0l[(size_t)HDIM * HDIM];
__device__ __nv_bfloat16 g_wt1h[(size_t)HDIM * HDIM];
__device__ __nv_bfloat16 g_wt1l[(size_t)HDIM * HDIM];
__device__ __nv_bfloat16 g_wt2h[(size_t)HDIM * HDIM];
__device__ __nv_bfloat16 g_wt2l[(size_t)HDIM * HDIM];

// ---------------------------------------------------------------------------
// Helpers (all sm_80-era PTX; nothing arch-accelerated)
// ---------------------------------------------------------------------------
__device__ __forceinline__ uint32_t smem_u32(const void* p) {
    uint32_t a;
    asm("{ .reg .u64 t; cvta.to.shared.u64 t, %1; cvt.u32.u64 %0, t; }"
        : "=r"(a) : "l"(p));
    return a;
}
__device__ __forceinline__ void ldmx4(uint32_t* r, uint32_t addr) {
    asm volatile("ldmatrix.sync.aligned.m8n8.x4.shared.b16 {%0,%1,%2,%3}, [%4];"
                 : "=r"(r[0]), "=r"(r[1]), "=r"(r[2]), "=r"(r[3]) : "r"(addr));
}
__device__ __forceinline__ void mma_bf16(float* d, const uint32_t* a,
                                         uint32_t b0, uint32_t b1) {
    asm volatile("mma.sync.aligned.m16n8k16.row.col.f32.bf16.bf16.f32 "
                 "{%0,%1,%2,%3}, {%4,%5,%6,%7}, {%8,%9}, {%0,%1,%2,%3};"
                 : "+f"(d[0]), "+f"(d[1]), "+f"(d[2]), "+f"(d[3])
                 : "r"(a[0]), "r"(a[1]), "r"(a[2]), "r"(a[3]), "r"(b0), "r"(b1));
}
__device__ __forceinline__ void cp16(uint32_t dst, const void* src) {
    asm volatile("cp.async.cg.shared.global [%0], [%1], 16;"
                 :: "r"(dst), "l"(src) : "memory");
}
#define CP_COMMIT() asm volatile("cp.async.commit_group;" ::: "memory")
#define CP_WAIT1()  asm volatile("cp.async.wait_group 1;" ::: "memory")

__device__ __forceinline__ void split2(float a, float b, uint32_t& hi, uint32_t& lo) {
    __nv_bfloat16 ha = __float2bfloat16_rn(a);
    __nv_bfloat16 hb = __float2bfloat16_rn(b);
    __nv_bfloat16 la = __float2bfloat16_rn(a - __bfloat162float(ha));
    __nv_bfloat16 lb = __float2bfloat16_rn(b - __bfloat162float(hb));
    __nv_bfloat162 H; H.x = ha; H.y = hb;
    __nv_bfloat162 L; L.x = la; L.y = lb;
    hi = *reinterpret_cast<uint32_t*>(&H);
    lo = *reinterpret_cast<uint32_t*>(&L);
}

// ---------------------------------------------------------------------------
// Prep A: elementwise fp32 -> bf16 hi/lo (row-major), float4 per thread
// ---------------------------------------------------------------------------
__global__ void split_rows(const float* __restrict__ X, size_t n4,
                           __nv_bfloat16* __restrict__ H,
                           __nv_bfloat16* __restrict__ L) {
    const size_t i = (size_t)blockIdx.x * blockDim.x + threadIdx.x;
    if (i >= n4) return;
    const float4 v = ((const float4*)X)[i];
    uint32_t h01, l01, h23, l23;
    split2(v.x, v.y, h01, l01);
    split2(v.z, v.w, h23, l23);
    ((uint2*)H)[i] = make_uint2(h01, h23);
    ((uint2*)L)[i] = make_uint2(l01, l23);
}

// ---------------------------------------------------------------------------
// Prep xm_part: xmp[64,1024] = x_m @ W0[0:1024,:]   (fp32, tiny, L2-resident)
// grid (HDIM/256, NM), block 256; coalesced over W0 columns.
// ---------------------------------------------------------------------------
__global__ void xm_gemm(const float* __restrict__ xm,
                        const float* __restrict__ W0,
                        float* __restrict__ xmp) {
    const int col = blockIdx.x * 256 + threadIdx.x;
    const int row = blockIdx.y;
    const float* xr = xm + (size_t)row * HDIM;
    float s0 = 0.f, s1 = 0.f, s2 = 0.f, s3 = 0.f;
    #pragma unroll 4
    for (int k = 0; k < HDIM; k += 4) {
        s0 += xr[k + 0] * W0[(size_t)(k + 0) * HDIM + col];
        s1 += xr[k + 1] * W0[(size_t)(k + 1) * HDIM + col];
        s2 += xr[k + 2] * W0[(size_t)(k + 2) * HDIM + col];
        s3 += xr[k + 3] * W0[(size_t)(k + 3) * HDIM + col];
    }
    xmp[(size_t)row * HDIM + col] = (s0 + s1) + (s2 + s3);
}

// ---------------------------------------------------------------------------
// Prep W: transpose + split [K x N] fp32 into PACKED swizzled k-16 blocks:
// block (ntile, ktile16) of 4096 B at ((n>>7)*(K/16) + (k>>4))*4096.
// ---------------------------------------------------------------------------
__global__ void transpose_split_pack(const float* __restrict__ W, int K, int N,
                                     __nv_bfloat16* __restrict__ Th,
                                     __nv_bfloat16* __restrict__ Tl) {
    __shared__ float tbuf[32][33];
    const int nb = blockIdx.x * 32, kb = blockIdx.y * 32;
    const int tx = threadIdx.x, ty = threadIdx.y;   // (32, 8)
    #pragma unroll
    for (int j = 0; j < 32; j += 8)
        tbuf[ty + j][tx] = W[(size_t)(kb + ty + j) * N + nb + tx];
    __syncthreads();
    #pragma unroll
    for (int j = 0; j < 32; j += 8) {
        const float x = tbuf[tx][ty + j];            // = W[kb+tx][nb+ty+j]
        const int k = kb + tx;
        const int n = nb + ty + j;
        const __nv_bfloat16 h = __float2bfloat16_rn(x);
        const __nv_bfloat16 l = __float2bfloat16_rn(x - __bfloat162float(h));
        const int lr = n & 127, kc = k & 15, ch = kc >> 3;
        const size_t off = ((size_t)(n >> 7) * (K / 16) + (k >> 4)) * 4096
                         + lr * 32 + ((ch ^ ((lr >> 2) & 1)) << 4) + (kc & 7) * 2;
        *(__nv_bfloat16*)((char*)Th + off) = h;
        *(__nv_bfloat16*)((char*)Tl + off) = l;
    }
}

// ---------------------------------------------------------------------------
// Split-bf16 GEMM layer, 3-stage cp.async pipeline (R13 skeleton, signature
// preserved).
//   GATHER: A rows gathered via op_idx from pre-split row-major bf16 x_op.
//           With KTOT=HDIM the Oh/Ol switch path (TSW) is statically dead;
//           the x_m half of L0 is hoisted into xm_part and added in the
//           epilogue through the `aux` slot.
//   else:   A from packed tiles, contiguous cp.async.
//   OUTPK:  write packed k-16 blocks for the next layer.
//   !OUTPK: fused final layer: dot output block with `aux` = W3, reduce to
//           per-(bx,row) partials (deterministic; 2 commutative atomics/row).
// ---------------------------------------------------------------------------
template <int KTOT, bool GATHER, bool OUTPK>
__global__ __launch_bounds__(NTHREADS)
void gemm_mma_kernel(const __nv_bfloat16* __restrict__ Ah,
                     const __nv_bfloat16* __restrict__ Al,
                     const __nv_bfloat16* __restrict__ Oh,
                     const __nv_bfloat16* __restrict__ Ol,
                     const __nv_bfloat16* __restrict__ WTh,
                     const __nv_bfloat16* __restrict__ WTl,
                     const float* __restrict__ bias,
                     const float* __restrict__ W0tail,     // rows 2048/2049 of W0
                     const float* __restrict__ aux,        // GATHER: xm_part; !OUTPK: W3
                     const float* __restrict__ job_srpt,
                     const float* __restrict__ pt,
                     const int* __restrict__ m_ids,
                     const int* __restrict__ op_idx,
                     const int* __restrict__ job_ids,
                     void* __restrict__ outH, void* __restrict__ outL) {
    extern __shared__ char sm[];
    const uint32_t sbase = smem_u32(sm);
    const int tid = threadIdx.x, wid = tid >> 5, lane = tid & 31;
    const int wm = wid >> 1, wn = wid & 1;
    const int n0 = blockIdx.x * BN, m0 = blockIdx.y * BM;
    constexpr int T = KTOT / BK;
    constexpr int TSW = HDIM / BK;            // dead when KTOT == HDIM (T == TSW)

    // B source: packed blocks, contiguous 4 KB per stage per matrix
    const char* srcBh = (const char*)WTh + (size_t)(n0 >> 7) * T * 4096 + tid * 16;
    const char* srcBl = (const char*)WTl + (size_t)(n0 >> 7) * T * 4096 + tid * 16;

    // A source
    const char *amH = nullptr, *amL = nullptr, *aoH = nullptr, *aoL = nullptr;
    const char *srcAh = nullptr, *srcAl = nullptr;
    const int arow = tid >> 1, ach = tid & 1;       // gather mapping: row, 16B chunk
    const int sb = (arow >> 2) & 1;                 // swizzle bit for this row
    const uint32_t dstA = arow * 32 + ((ach ^ sb) << 4);   // swizzled dest offset
    if constexpr (GATHER) {
        const int m = m0 + arow;
        amH = (const char*)(Ah + (size_t)op_idx[m] * HDIM);
        amL = (const char*)(Al + (size_t)op_idx[m] * HDIM);
        aoH = (const char*)(Oh + (size_t)op_idx[m] * HDIM);
        aoL = (const char*)(Ol + (size_t)op_idx[m] * HDIM);
    } else {
        srcAh = (const char*)Ah + (size_t)(m0 >> 7) * T * 4096 + tid * 16;
        srcAl = (const char*)Al + (size_t)(m0 >> 7) * T * 4096 + tid * 16;
    }

    float acc[2][8][4];
    #pragma unroll
    for (int i = 0; i < 2; ++i)
        #pragma unroll
        for (int j = 0; j < 8; ++j)
            #pragma unroll
            for (int r = 0; r < 4; ++r) acc[i][j][r] = 0.f;

    auto cpStage = [&](int kt, int slot) {
        const uint32_t d = sbase + slot * ST_STRIDE;
        const size_t o = (size_t)kt * 4096;
        cp16(d + ST_BH + tid * 16, srcBh + o);
        cp16(d + ST_BL + tid * 16, srcBl + o);
        if constexpr (GATHER) {
            const char* sh = amH;
            const char* sl = amL;
            int kk = kt;
            if (kt >= TSW) { sh = aoH; sl = aoL; kk = kt - TSW; }   // dead: T==TSW
            const size_t so = (size_t)kk * 32 + ach * 16;   // bytes within bf16 row
            cp16(d + ST_AH + dstA, sh + so);
            cp16(d + ST_AL + dstA, sl + so);
        } else {
            cp16(d + ST_AH + tid * 16, srcAh + o);
            cp16(d + ST_AL + tid * 16, srcAl + o);
        }
    };

    // ---- prologue ----
    cpStage(0, 0); CP_COMMIT();
    cpStage(1, 1); CP_COMMIT();

    // per-lane ldmatrix offset (row + swizzled k-chunk)
    const uint32_t lofs = (lane & 15) * 32 + (((lane >> 4) ^ ((lane >> 2) & 1)) << 4);

    for (int t = 0; t < T; ++t) {
        CP_WAIT1();                 // stage t complete (newest group may pend)
        __syncthreads();            // all warps done computing stage t-1
        if (t + 2 < T) cpStage(t + 2, (t + 2) % 3);   // refills slot (t-1)%3
        CP_COMMIT();                // unconditional: keeps wait_group(1) semantics

        const uint32_t st = sbase + (t % 3) * ST_STRIDE;
        uint32_t ah[2][4], al[2][4], bh[4][4], bl[4][4];
        #pragma unroll
        for (int mt = 0; mt < 2; ++mt) {
            const uint32_t ra = st + ST_AH + wm * 1024 + mt * 512 + lofs;
            ldmx4(ah[mt], ra);
            ldmx4(al[mt], ra + (ST_AL - ST_AH));
        }
        #pragma unroll
        for (int p = 0; p < 4; ++p) {
            const uint32_t rb = st + ST_BH + wn * 2048 + p * 512 + lofs;
            ldmx4(bh[p], rb);
            ldmx4(bl[p], rb + (ST_BL - ST_BH));
        }
        #pragma unroll
        for (int mt = 0; mt < 2; ++mt)
            #pragma unroll
            for (int nt = 0; nt < 8; ++nt) {
                const int p = nt >> 1, o = nt & 1;
                mma_bf16(acc[mt][nt], ah[mt], bh[p][o], bh[p][2 + o]);
                mma_bf16(acc[mt][nt], ah[mt], bl[p][o], bl[p][2 + o]);
                mma_bf16(acc[mt][nt], al[mt], bh[p][o], bh[p][2 + o]);
            }
    }

    // ---- epilogue ----
    const int gq = lane >> 2, tg = lane & 3;

    float* sPart = (float*)sm;      // aliases stage 0 (free after loop + sync)
    if constexpr (!OUTPK) {
        __syncthreads();            // all warps out of the main loop (smem reuse)
        if (tid < BM) sPart[tid] = 0.f;
        __syncthreads();
    }

    #pragma unroll
    for (int mt = 0; mt < 2; ++mt) {
        const int lr0 = wm * 32 + mt * 16 + gq;       // local row in [0,128)
        const int lr1 = lr0 + 8;
        const int er0 = m0 + lr0, er1 = m0 + lr1;
        float js0 = 0.f, pv0 = 0.f, js1 = 0.f, pv1 = 0.f;
        const float *xm0 = nullptr, *xm1 = nullptr;
        if constexpr (GATHER) {
            js0 = job_srpt[job_ids[er0]]; pv0 = pt[er0];
            js1 = job_srpt[job_ids[er1]]; pv1 = pt[er1];
            xm0 = aux + (size_t)m_ids[er0] * HDIM;    // hoisted x_m @ W0-upper
            xm1 = aux + (size_t)m_ids[er1] * HDIM;
        }
        float p0 = 0.f, p1 = 0.f;                     // fused-dot partials
        #pragma unroll
        for (int nt = 0; nt < 8; ++nt) {
            const int nc = n0 + wn * 64 + nt * 8 + tg * 2;
            const float bz0 = bias[nc], bz1 = bias[nc + 1];
            float e00 = 0.f, e01 = 0.f, e10 = 0.f, e11 = 0.f;
            if constexpr (GATHER) {
                const float wa0 = W0tail[nc], wa1 = W0tail[nc + 1];
                const float wb0 = W0tail[HDIM + nc], wb1 = W0tail[HDIM + nc + 1];
                e00 = js0 * wa0 + pv0 * wb0 + xm0[nc];
                e01 = js0 * wa1 + pv0 * wb1 + xm0[nc + 1];
                e10 = js1 * wa0 + pv1 * wb0 + xm1[nc];
                e11 = js1 * wa1 + pv1 * wb1 + xm1[nc + 1];
            }
            float v00 = acc[mt][nt][0] + bz0 + e00;
            float v01 = acc[mt][nt][1] + bz1 + e01;
            float v10 = acc[mt][nt][2] + bz0 + e10;
            float v11 = acc[mt][nt][3] + bz1 + e11;
            v00 = v00 > 0.f ? v00 : 0.01f * v00;
            v01 = v01 > 0.f ? v01 : 0.01f * v01;
            v10 = v10 > 0.f ? v10 : 0.01f * v10;
            v11 = v11 > 0.f ? v11 : 0.01f * v11;
            if constexpr (OUTPK) {
                // packed k-16 blocks for the next layer (its K = HDIM)
                const size_t blk = ((size_t)blockIdx.y * (HDIM / 16) + (nc >> 4)) * 4096;
                const uint32_t sw = ((((nc >> 3) & 1) ^ ((lr0 >> 2) & 1)) << 4);
                const uint32_t o0 = lr0 * 32 + sw + (nc & 7) * 2;
                const uint32_t o1 = lr1 * 32 + sw + (nc & 7) * 2;
                uint32_t h0, l0, h1, l1;
                split2(v00, v01, h0, l0);
                split2(v10, v11, h1, l1);
                *(uint32_t*)((char*)outH + blk + o0) = h0;
                *(uint32_t*)((char*)outL + blk + o0) = l0;
                *(uint32_t*)((char*)outH + blk + o1) = h1;
                *(uint32_t*)((char*)outL + blk + o1) = l1;
            } else {
                const float w0 = aux[nc], w1 = aux[nc + 1];
                p0 += v00 * w0 + v01 * w1;
                p1 += v10 * w0 + v11 * w1;
            }
        }
        if constexpr (!OUTPK) {
            p0 += __shfl_xor_sync(0xffffffffu, p0, 1);
            p0 += __shfl_xor_sync(0xffffffffu, p0, 2);
            p1 += __shfl_xor_sync(0xffffffffu, p1, 1);
            p1 += __shfl_xor_sync(0xffffffffu, p1, 2);
            if (tg == 0) {
                // exactly 2 contributions per row (wn=0,1): commutative -> deterministic
                atomicAdd(&sPart[lr0], p0);
                atomicAdd(&sPart[lr1], p1);
            }
        }
    }

    if constexpr (!OUTPK) {
        __syncthreads();
        float* part = (float*)outH;   // g_part
        if (tid < BM)
            part[(size_t)blockIdx.x * NAVAIL + m0 + tid] = sPart[tid];
    }
}

// ---------------------------------------------------------------------------
// Deterministic 8-way reduce of per-bx partial dots -> scores (b3 dropped:
// softmax/argmax are invariant to the constant shift).
// ---------------------------------------------------------------------------
__global__ void reduce_scores(const float* __restrict__ part,
                              float* __restrict__ scores) {
    const int m = blockIdx.x * blockDim.x + threadIdx.x;
    if (m >= NAVAIL) return;
    float s = 0.f;
    #pragma unroll
    for (int b = 0; b < NBX; ++b)
        s += part[(size_t)b * NAVAIL + m];
    scores[m] = s;
}

// ---------------------------------------------------------------------------
// Softmax + argmax (first-max semantics), single block.
// ---------------------------------------------------------------------------
__global__ void softmax_kernel(const float* __restrict__ scores,
                               float* __restrict__ out, int out_size) {
    const int tid = threadIdx.x;
    const int lane = tid & 31;
    const int wid = tid >> 5;
    __shared__ float red_f[32];
    __shared__ int   red_i[32];
    __shared__ float red_s[32];

    float bmax = -INFINITY;
    int bidx = 0x7fffffff;
    for (int i = tid; i < NAVAIL; i += 1024) {
        const float v = scores[i];
        if (v > bmax) { bmax = v; bidx = i; }
    }
    #pragma unroll
    for (int off = 16; off > 0; off >>= 1) {
        const float om = __shfl_down_sync(0xffffffffu, bmax, off);
        const int oi = __shfl_down_sync(0xffffffffu, bidx, off);
        if (om > bmax || (om == bmax && oi < bidx)) { bmax = om; bidx = oi; }
    }
    if (lane == 0) { red_f[wid] = bmax; red_i[wid] = bidx; }
    __syncthreads();
    if (tid < 32) {
        bmax = red_f[tid];
        bidx = red_i[tid];
        #pragma unroll
        for (int off = 16; off > 0; off >>= 1) {
            const float om = __shfl_down_sync(0xffffffffu, bmax, off);
            const int oi = __shfl_down_sync(0xffffffffu, bidx, off);
            if (om > bmax || (om == bmax && oi < bidx)) { bmax = om; bidx = oi; }
        }
        if (tid == 0) { red_f[0] = bmax; red_i[0] = bidx; }
    }
    __syncthreads();
    const float gmax = red_f[0];
    const int gidx = red_i[0];

    float s = 0.f;
    for (int i = tid; i < NAVAIL; i += 1024) {
        const float e = expf(scores[i] - gmax);
        out[i] = e;
        s += e;
    }
    #pragma unroll
    for (int off = 16; off > 0; off >>= 1)
        s += __shfl_down_sync(0xffffffffu, s, off);
    if (lane == 0) red_s[wid] = s;
    __syncthreads();
    if (tid < 32) {
        s = red_s[tid];
        #pragma unroll
        for (int off = 16; off > 0; off >>= 1)
            s += __shfl_down_sync(0xffffffffu, s, off);
        if (tid == 0) red_s[0] = s;
    }
    __syncthreads();
    const float inv = 1.0f / red_s[0];
    for (int i = tid; i < NAVAIL; i += 1024)
        out[i] *= inv;
    for (int i = NAVAIL + tid; i < out_size; i += 1024)
        out[i] = (float)gidx;
}

// ---------------------------------------------------------------------------
// Launch. inputs: x_m, x_op, job_srpt, pt, W0, b0, W1, b1, W2, b2, W3, b3,
//                 m_ids, op_idx, job_ids
// Host API surface: cudaGetSymbolAddress + launches only (NO attr calls).
// ---------------------------------------------------------------------------
extern "C" void kernel_launch(void* const* d_in, const int* in_sizes, int n_in,
                              void* d_out, int out_size) {
    const float* x_m      = (const float*)d_in[0];
    const float* x_op     = (const float*)d_in[1];
    const float* job_srpt = (const float*)d_in[2];
    const float* pt       = (const float*)d_in[3];
    const float* W0       = (const float*)d_in[4];
    const float* b0       = (const float*)d_in[5];
    const float* W1       = (const float*)d_in[6];
    const float* b1       = (const float*)d_in[7];
    const float* W2       = (const float*)d_in[8];
    const float* b2       = (const float*)d_in[9];
    const float* W3       = (const float*)d_in[10];
    const int*   m_ids    = (const int*)d_in[12];
    const int*   op_idx   = (const int*)d_in[13];
    const int*   job_ids  = (const int*)d_in[14];
    float* out = (float*)d_out;

    float *sc, *partp, *xmp;
    __nv_bfloat16 *xoh, *xol, *a0h, *a0l, *a1h, *a1l;
    __nv_bfloat16 *w0h, *w0l, *w1h, *w1l, *w2h, *w2l;
    cudaGetSymbolAddress((void**)&sc, g_scores);
    cudaGetSymbolAddress((void**)&partp, g_part);
    cudaGetSymbolAddress((void**)&xmp, g_xmp);
    cudaGetSymbolAddress((void**)&xoh, g_xoh);
    cudaGetSymbolAddress((void**)&xol, g_xol);
    cudaGetSymbolAddress((void**)&a0h, g_a0h);
    cudaGetSymbolAddress((void**)&a0l, g_a0l);
    cudaGetSymbolAddress((void**)&a1h, g_a1h);
    cudaGetSymbolAddress((void**)&a1l, g_a1l);
    cudaGetSymbolAddress((void**)&w0h, g_wt0h);
    cudaGetSymbolAddress((void**)&w0l, g_wt0l);
    cudaGetSymbolAddress((void**)&w1h, g_wt1h);
    cudaGetSymbolAddress((void**)&w1l, g_wt1l);
    cudaGetSymbolAddress((void**)&w2h, g_wt2h);
    cudaGetSymbolAddress((void**)&w2l, g_wt2l);

    // prep: xm_part fp32 GEMM + split x_op + pack weights (off critical path)
    {
        xm_gemm<<<dim3(HDIM / 256, NM), 256>>>(x_m, W0, xmp);
        const size_t no4 = (size_t)NOP * HDIM / 4;
        split_rows<<<(int)((no4 + 255) / 256), 256>>>(x_op, no4, xoh, xol);
        dim3 thr(32, 8);
        // pack only the x_op half of W0: rows 1024..2047
        transpose_split_pack<<<dim3(HDIM / 32, HDIM / 32), thr>>>(
            W0 + (size_t)HDIM * HDIM, HDIM, HDIM, w0h, w0l);
        transpose_split_pack<<<dim3(HDIM / 32, HDIM / 32), thr>>>(W1, HDIM, HDIM, w1h, w1l);
        transpose_split_pack<<<dim3(HDIM / 32, HDIM / 32), thr>>>(W2, HDIM, HDIM, w2h, w2l);
    }

    const dim3 grid(HDIM / BN, NAVAIL / BM);   // (8, 256)
    const float* W0tail = W0 + (size_t)2048 * HDIM;   // rows 2048, 2049

    // L0: K=1024 (x_op half only); x_m half comes from xm_part in the epilogue
    gemm_mma_kernel<HDIM, true, true><<<grid, NTHREADS, SMEM_BYTES>>>(
        xoh, xol, xoh, xol, w0h, w0l, b0, W0tail, xmp, job_srpt, pt,
        m_ids, op_idx, job_ids, a0h, a0l);
    gemm_mma_kernel<HDIM, false, true><<<grid, NTHREADS, SMEM_BYTES>>>(
        a0h, a0l, nullptr, nullptr, w1h, w1l, b1, nullptr, nullptr, nullptr,
        nullptr, nullptr, nullptr, nullptr, a1h, a1l);
    // final layer: fused h2 dot W3 -> per-bx partial scores
    gemm_mma_kernel<HDIM, false, false><<<grid, NTHREADS, SMEM_BYTES>>>(
        a1h, a1l, nullptr, nullptr, w2h, w2l, b2, nullptr, W3, nullptr,
        nullptr, nullptr, nullptr, nullptr, partp, nullptr);

    reduce_scores<<<NAVAIL / 256, 256>>>(partp, sc);
    softmax_kernel<<<1, 1024>>>(sc, out, out_size);
}